// round 9
// baseline (speedup 1.0000x reference)
#include <cuda_runtime.h>
#include <cuda_fp16.h>
#include <math.h>
#include <stdint.h>

#define BATCH 4
#define DIM   512
#define MLEN  4096
#define HEADS 8
#define HD    64
#define KCONV 4608
#define YROWS 4356
#define SMEMB  61440   // hgemm: 3 * (10240 + 10240)
#define SMEMB2 92160   // hgemm256: 3 * (10240 + 20480)

// ---------------- static scratch ----------------
__device__ float  g_kv  [BATCH*DIM*MLEN];       // k only (fp32 [o][m])
__device__ float  g_q   [BATCH*DIM*MLEN];
__device__ float  g_part[BATCH*HEADS*8*HD*HD];
__device__ float  g_nsq [BATCH*HEADS*8*2*HD];
__device__ float  g_attn[BATCH*HEADS*HD*HD];
__device__ __half g_xTh [BATCH*MLEN*DIM];
__device__ __half g_yTh [BATCH*YROWS*DIM];
__device__ __half g_vTh [BATCH*MLEN*DIM];
__device__ __half g_wkvh[2*DIM*DIM];
__device__ __half g_wqTh[DIM*DIM];
__device__ __half g_wdwh[9*DIM*DIM];
__device__ __half g_wc2h[DIM*KCONV];
__device__ __half g_w2h [BATCH*DIM*DIM];

// ---------------- helpers ----------------
__device__ __forceinline__ void cpa16(uint32_t d, const void* s){
    asm volatile("cp.async.cg.shared.global [%0], [%1], 16;" :: "r"(d), "l"(s));
}
#define CP_COMMIT() asm volatile("cp.async.commit_group;")
#define CP_WAIT1()  asm volatile("cp.async.wait_group 1;")

__device__ __forceinline__ void mma16(float& c0, float& c1, float& c2, float& c3,
                                      uint32_t a0, uint32_t a1, uint32_t a2, uint32_t a3,
                                      uint32_t b0, uint32_t b1){
    asm volatile(
        "mma.sync.aligned.m16n8k16.row.col.f32.f16.f16.f32 "
        "{%0,%1,%2,%3}, {%4,%5,%6,%7}, {%8,%9}, {%0,%1,%2,%3};"
        : "+f"(c0), "+f"(c1), "+f"(c2), "+f"(c3)
        : "r"(a0), "r"(a1), "r"(a2), "r"(a3), "r"(b0), "r"(b1));
}
__device__ __forceinline__ void ldsm4(uint32_t& r0, uint32_t& r1, uint32_t& r2, uint32_t& r3,
                                      uint32_t a){
    asm volatile("ldmatrix.sync.aligned.m8n8.x4.shared.b16 {%0,%1,%2,%3}, [%4];"
        : "=r"(r0), "=r"(r1), "=r"(r2), "=r"(r3) : "r"(a));
}

// ============ hgemm: 128x128, BK=32, occ 2 (R7-validated) ============
// OUTM: 0 fp32 C; 1 fp16 C; 2 kv-special (bm<512 -> fp32 k; else vT fp16)
template<int CONV, int OUTM>
__global__ __launch_bounds__(256, 2)
void hgemm(const __half* __restrict__ A, long lA,
           const __half* __restrict__ B, long lB,
           void* __restrict__ Cv, long lC, int ldC,
           int M, int K, __half* __restrict__ VT)
{
    extern __shared__ __half sh[];
    const uint32_t smb = (uint32_t)__cvta_generic_to_shared(sh);
    A += (long)blockIdx.z * lA;
    B += (long)blockIdx.z * lB;
    const int bm = blockIdx.y * 128, bn = blockIdx.x * 128;
    const int tid = threadIdx.x, lane = tid & 31, warp = tid >> 5;
    const int wm = (warp >> 2) * 64, wn = (warp & 3) * 32;
    const int g = lane >> 2, t = lane & 3;
    const int lrow = tid >> 1, lco = (tid & 1) * 16;

    int ph = 0, pw = 0;
    if (CONV) { const int n = bn + lrow; ph = n >> 6; pw = n & 63; }

    const uint32_t aOff = (uint32_t)((wm + (lane & 15)) * 80 + (lane >> 4) * 16);
    const uint32_t bOff = (uint32_t)((wn + (lane & 7) + ((lane >> 4) << 3)) * 80
                                     + ((lane >> 3) & 1) * 16);

    float acc[4][4][4];
#pragma unroll
    for (int i = 0; i < 4; i++)
#pragma unroll
        for (int j = 0; j < 4; j++)
#pragma unroll
            for (int r = 0; r < 4; r++) acc[i][j][r] = 0.f;

    const int T = K >> 5;

    auto load = [&](int s, int tt){
        const int k0 = tt << 5;
        const uint32_t sb = smb + (uint32_t)s * 20480u;
        const __half* asrc = A + (long)(bm + lrow) * K + k0 + lco;
        const uint32_t adst = sb + (uint32_t)lrow * 80u + (uint32_t)lco * 2u;
        cpa16(adst,       asrc);
        cpa16(adst + 16u, asrc + 8);
        const __half* bsrc;
        if (CONV) {
            const int r = k0 >> 9;
            const int dyr = r / 3, dxr = r - 3 * dyr;
            bsrc = B + ((long)((ph + dyr) * 66 + pw + dxr)) * DIM + (k0 & 511) + lco;
        } else {
            bsrc = B + (long)(bn + lrow) * K + k0 + lco;
        }
        const uint32_t bdst = sb + 10240u + (uint32_t)lrow * 80u + (uint32_t)lco * 2u;
        cpa16(bdst,       bsrc);
        cpa16(bdst + 16u, bsrc + 8);
    };

    load(0, 0); CP_COMMIT();
    load(1, 1); CP_COMMIT();

    for (int tt = 0; tt < T; tt++) {
        const int s = tt % 3;
        CP_WAIT1();
        __syncthreads();
        if (tt + 2 < T) load((tt + 2) % 3, tt + 2);
        CP_COMMIT();

        const uint32_t sb = smb + (uint32_t)s * 20480u;
#pragma unroll
        for (int ks = 0; ks < 2; ks++) {
            const uint32_t kb = (uint32_t)ks * 32u;
            uint32_t af[4][4], bf[2][4];
#pragma unroll
            for (int mi = 0; mi < 4; mi++)
                ldsm4(af[mi][0], af[mi][1], af[mi][2], af[mi][3],
                      sb + aOff + (uint32_t)mi * 1280u + kb);
            ldsm4(bf[0][0], bf[0][1], bf[0][2], bf[0][3], sb + 10240u + bOff + kb);
            ldsm4(bf[1][0], bf[1][1], bf[1][2], bf[1][3], sb + 10240u + bOff + 1280u + kb);
#pragma unroll
            for (int mi = 0; mi < 4; mi++)
#pragma unroll
                for (int ni = 0; ni < 4; ni++) {
                    const int p = ni >> 1, q2 = (ni & 1) * 2;
                    mma16(acc[mi][ni][0], acc[mi][ni][1], acc[mi][ni][2], acc[mi][ni][3],
                          af[mi][0], af[mi][1], af[mi][2], af[mi][3],
                          bf[p][q2], bf[p][q2 + 1]);
                }
        }
    }

    const bool vpath = (OUTM == 2) && (bm >= 512);
    if (OUTM == 1) {
        __half* C = (__half*)Cv + (long)blockIdx.z * lC;
#pragma unroll
        for (int mi = 0; mi < 4; mi++) {
            const int row0 = bm + wm + mi * 16 + g;
#pragma unroll
            for (int ni = 0; ni < 4; ni++) {
                const int col = bn + wn + ni * 8 + 2 * t;
                *(__half2*)(C + (long)row0 * ldC + col) =
                    __floats2half2_rn(acc[mi][ni][0], acc[mi][ni][1]);
                *(__half2*)(C + (long)(row0 + 8) * ldC + col) =
                    __floats2half2_rn(acc[mi][ni][2], acc[mi][ni][3]);
            }
        }
    } else if (!vpath) {
        float* C = (float*)Cv + (long)blockIdx.z * lC;
#pragma unroll
        for (int mi = 0; mi < 4; mi++) {
            const int row0 = bm + wm + mi * 16 + g;
#pragma unroll
            for (int ni = 0; ni < 4; ni++) {
                const int col = bn + wn + ni * 8 + 2 * t;
                *(float2*)(C + (long)row0 * ldC + col) =
                    make_float2(acc[mi][ni][0], acc[mi][ni][1]);
                *(float2*)(C + (long)(row0 + 8) * ldC + col) =
                    make_float2(acc[mi][ni][2], acc[mi][ni][3]);
            }
        }
    } else {
        __syncthreads();
#pragma unroll
        for (int mi = 0; mi < 4; mi++) {
            const int r0 = wm + mi * 16 + g;
#pragma unroll
            for (int ni = 0; ni < 4; ni++) {
                const int c0 = wn + ni * 8 + 2 * t;
                sh[(c0    ) * 136 + r0    ] = __float2half_rn(acc[mi][ni][0]);
                sh[(c0 + 1) * 136 + r0    ] = __float2half_rn(acc[mi][ni][1]);
                sh[(c0    ) * 136 + r0 + 8] = __float2half_rn(acc[mi][ni][2]);
                sh[(c0 + 1) * 136 + r0 + 8] = __float2half_rn(acc[mi][ni][3]);
            }
        }
        __syncthreads();
        __half* vt = VT + (long)blockIdx.z * MLEN * DIM;
        const int ml = tid >> 1, ho = (tid & 1) * 64;
        __half* dst = vt + (long)(bn + ml) * DIM + (bm - 512) + ho;
        const __half* srcp = sh + ml * 136 + ho;
#pragma unroll
        for (int i = 0; i < 8; i++)
            *(uint4*)(dst + i * 8) = *(const uint4*)(srcp + i * 8);
    }
}

// ============ hgemm256: conv implicit GEMM, 128x256, BK=32, occ 1, fp32 out ==
__global__ __launch_bounds__(256, 1)
void hgemm256(const __half* __restrict__ A,
              const __half* __restrict__ B, long lB,
              float* __restrict__ C, long lC)
{
    extern __shared__ __half sh[];
    const uint32_t smb = (uint32_t)__cvta_generic_to_shared(sh);
    B += (long)blockIdx.z * lB;
    const int bm = blockIdx.y * 128, bn = blockIdx.x * 256;
    const int tid = threadIdx.x, lane = tid & 31, warp = tid >> 5;
    const int wm = (warp >> 2) * 64, wn = (warp & 3) * 64;
    const int g = lane >> 2, t = lane & 3;
    const int lrow = tid >> 1, lco = (tid & 1) * 16;
    const int n = bn + tid, ph = n >> 6, pw = n & 63;

    const uint32_t aOff = (uint32_t)((wm + (lane & 15)) * 80 + (lane >> 4) * 16);
    const uint32_t bOff = (uint32_t)((wn + (lane & 7) + ((lane >> 4) << 3)) * 80
                                     + ((lane >> 3) & 1) * 16);

    float acc[4][8][4];
#pragma unroll
    for (int i = 0; i < 4; i++)
#pragma unroll
        for (int j = 0; j < 8; j++)
#pragma unroll
            for (int r = 0; r < 4; r++) acc[i][j][r] = 0.f;

    const int T = KCONV >> 5;   // 144

    auto load = [&](int s, int tt){
        const int k0 = tt << 5;
        const uint32_t sb = smb + (uint32_t)s * 30720u;
        const __half* asrc = A + (long)(bm + lrow) * KCONV + k0 + lco;
        const uint32_t adst = sb + (uint32_t)lrow * 80u + (uint32_t)lco * 2u;
        cpa16(adst,       asrc);
        cpa16(adst + 16u, asrc + 8);
        const int r = k0 >> 9;
        const int dyr = r / 3, dxr = r - 3 * dyr;
        const __half* bsrc = B + ((long)((ph + dyr) * 66 + pw + dxr)) * DIM + (k0 & 511);
        const uint32_t bdst = sb + 10240u + (uint32_t)tid * 80u;
#pragma unroll
        for (int i = 0; i < 4; i++)
            cpa16(bdst + (uint32_t)i * 16u, bsrc + i * 8);
    };

    load(0, 0); CP_COMMIT();
    load(1, 1); CP_COMMIT();

    for (int tt = 0; tt < T; tt++) {
        const int s = tt % 3;
        CP_WAIT1();
        __syncthreads();
        if (tt + 2 < T) load((tt + 2) % 3, tt + 2);
        CP_COMMIT();

        const uint32_t sb = smb + (uint32_t)s * 30720u;
#pragma unroll
        for (int ks = 0; ks < 2; ks++) {
            const uint32_t kb = (uint32_t)ks * 32u;
            uint32_t af[4][4], bf[4][4];
#pragma unroll
            for (int mi = 0; mi < 4; mi++)
                ldsm4(af[mi][0], af[mi][1], af[mi][2], af[mi][3],
                      sb + aOff + (uint32_t)mi * 1280u + kb);
#pragma unroll
            for (int p = 0; p < 4; p++)
                ldsm4(bf[p][0], bf[p][1], bf[p][2], bf[p][3],
                      sb + 10240u + bOff + (uint32_t)p * 1280u + kb);
#pragma unroll
            for (int mi = 0; mi < 4; mi++)
#pragma unroll
                for (int ni = 0; ni < 8; ni++) {
                    const int p = ni >> 1, q2 = (ni & 1) * 2;
                    mma16(acc[mi][ni][0], acc[mi][ni][1], acc[mi][ni][2], acc[mi][ni][3],
                          af[mi][0], af[mi][1], af[mi][2], af[mi][3],
                          bf[p][q2], bf[p][q2 + 1]);
                }
        }
    }

    float* Cp = C + (long)blockIdx.z * lC;
#pragma unroll
    for (int mi = 0; mi < 4; mi++) {
        const int row0 = bm + wm + mi * 16 + g;
#pragma unroll
        for (int ni = 0; ni < 8; ni++) {
            const int col = bn + wn + ni * 8 + 2 * t;
            *(float2*)(Cp + (long)row0 * MLEN + col) =
                make_float2(acc[mi][ni][0], acc[mi][ni][1]);
            *(float2*)(Cp + (long)(row0 + 8) * MLEN + col) =
                make_float2(acc[mi][ni][2], acc[mi][ni][3]);
        }
    }
}

// ---------------- prep / transpose kernels ----------------
__global__ void conv_h(const float* __restrict__ s, __half* __restrict__ d, int n){
    const int i = blockIdx.x * 256 + threadIdx.x;
    if (i < n) d[i] = __float2half_rn(s[i]);
}

template<int PADY>
__global__ void transpose_h(const float* __restrict__ S, long lS,
                            __half* __restrict__ D, long lD, int R, int C)
{
    __shared__ float tle[32][33];
    S += (long)blockIdx.z * lS;
    D += (long)blockIdx.z * lD;
    const int m0 = blockIdx.x * 32, c0 = blockIdx.y * 32;
    const int tx = threadIdx.x & 31, ty = threadIdx.x >> 5;
#pragma unroll
    for (int i = ty; i < 32; i += 8)
        tle[i][tx] = S[(long)(c0 + i) * C + m0 + tx];
    __syncthreads();
    const long prow = PADY ? (long)(m0 + 2 * (m0 >> 6) + 67) : (long)m0;
#pragma unroll
    for (int i = ty; i < 32; i += 8)
        D[(prow + i) * R + c0 + tx] = __float2half_rn(tle[tx][i]);
}

__global__ void ypad_zero_h(__half* __restrict__ yT)
{
    const int idx = blockIdx.x;
    int row;
    if (idx < 66) row = idx;
    else if (idx < 132) row = 65 * 66 + (idx - 66);
    else { const int i = idx - 132; row = (1 + (i >> 1)) * 66 + (i & 1) * 65; }
    uint32_t* p = (uint32_t*)(yT + ((long)blockIdx.y * YROWS + row) * DIM);
    p[threadIdx.x] = 0u;
}

__global__ void prep_wdw_h(const float* __restrict__ wdw, __half* __restrict__ wdwh)
{
    __shared__ float s[KCONV];
    const int o2 = blockIdx.x;
    const float* src = wdw + (long)o2 * KCONV;
    for (int i = threadIdx.x; i < KCONV; i += 256) s[i] = src[i];
    __syncthreads();
    for (int i = threadIdx.x; i < KCONV; i += 256) {
        const int r = i >> 9, o = i & 511;
        wdwh[((long)r * DIM + o2) * DIM + o] = __float2half_rn(s[o * 9 + r]);
    }
}

// ---------------- attention logits + fused sumsq (R7-validated) -----------
__global__ __launch_bounds__(256)
void attn_partial_kernel(const float* __restrict__ Q, const float* __restrict__ KV,
                         float* __restrict__ part, float* __restrict__ nsq)
{
    const int mc = blockIdx.x, h = blockIdx.y, b = blockIdx.z;
    const float* Qp = Q  + ((long)(b * DIM + h * HD)) * MLEN + mc * 512;
    const float* Kp = KV + ((long)(b * DIM + h * HD)) * MLEN + mc * 512;
    __shared__ float sq[32][64];
    __shared__ float sk[32][64];
    const int tid = threadIdx.x, row = tid >> 2, mg = (tid & 3) * 8;
    const int tx = tid & 15, ty = tid >> 4;
    float acc[4][4];
#pragma unroll
    for (int i = 0; i < 4; i++)
#pragma unroll
        for (int j = 0; j < 4; j++) acc[i][j] = 0.f;
    float ssq = 0.f, ssk = 0.f;
    for (int mt = 0; mt < 512; mt += 32) {
        float4 a0 = *(const float4*)(Qp + (long)row * MLEN + mt + mg);
        float4 a1 = *(const float4*)(Qp + (long)row * MLEN + mt + mg + 4);
        sq[mg+0][row]=a0.x; sq[mg+1][row]=a0.y; sq[mg+2][row]=a0.z; sq[mg+3][row]=a0.w;
        sq[mg+4][row]=a1.x; sq[mg+5][row]=a1.y; sq[mg+6][row]=a1.z; sq[mg+7][row]=a1.w;
        ssq += a0.x*a0.x+a0.y*a0.y+a0.z*a0.z+a0.w*a0.w + a1.x*a1.x+a1.y*a1.y+a1.z*a1.z+a1.w*a1.w;
        float4 b0 = *(const float4*)(Kp + (long)row * MLEN + mt + mg);
        float4 b1 = *(const float4*)(Kp + (long)row * MLEN + mt + mg + 4);
        sk[mg+0][row]=b0.x; sk[mg+1][row]=b0.y; sk[mg+2][row]=b0.z; sk[mg+3][row]=b0.w;
        sk[mg+4][row]=b1.x; sk[mg+5][row]=b1.y; sk[mg+6][row]=b1.z; sk[mg+7][row]=b1.w;
        ssk += b0.x*b0.x+b0.y*b0.y+b0.z*b0.z+b0.w*b0.w + b1.x*b1.x+b1.y*b1.y+b1.z*b1.z+b1.w*b1.w;
        __syncthreads();
#pragma unroll
        for (int mm = 0; mm < 32; mm++) {
            float ra[4], rb[4];
#pragma unroll
            for (int i = 0; i < 4; i++) ra[i] = sq[mm][ty*4+i];
#pragma unroll
            for (int j = 0; j < 4; j++) rb[j] = sk[mm][tx*4+j];
#pragma unroll
            for (int i = 0; i < 4; i++)
#pragma unroll
                for (int j = 0; j < 4; j++) acc[i][j] += ra[i]*rb[j];
        }
        __syncthreads();
    }
    ssq += __shfl_xor_sync(~0u, ssq, 1); ssq += __shfl_xor_sync(~0u, ssq, 2);
    ssk += __shfl_xor_sync(~0u, ssk, 1); ssk += __shfl_xor_sync(~0u, ssk, 2);
    if ((tid & 3) == 0) {
        const long nb = (((long)(b*HEADS + h))*8 + mc) * 2 * HD;
        nsq[nb + row] = ssq;
        nsq[nb + HD + row] = ssk;
    }
    float* pp = part + ((((long)(b*HEADS + h))*8 + mc)*HD + ty*4)*HD + tx*4;
#pragma unroll
    for (int i = 0; i < 4; i++)
#pragma unroll
        for (int j = 0; j < 4; j++) pp[i*HD + j] = acc[i][j];
}

__global__ void softmax_kernel(const float* __restrict__ part, const float* __restrict__ nsq,
                               const float* __restrict__ temp, float* __restrict__ attn)
{
    const int row = blockIdx.x;
    const int b = row >> 9, h = (row >> 6) & 7, c = row & 63;
    const int lane = threadIdx.x;
    const long nb = ((long)(b*HEADS + h)) * 8 * 2 * HD;
    float sqs = 0.f, sk0 = 0.f, sk1 = 0.f;
#pragma unroll
    for (int mc = 0; mc < 8; mc++) {
        sqs += nsq[nb + mc*2*HD + c];
        sk0 += nsq[nb + mc*2*HD + HD + lane];
        sk1 += nsq[nb + mc*2*HD + HD + lane + 32];
    }
    const float rq  = 1.f / fmaxf(sqrtf(sqs), 1e-12f);
    const float rk0 = 1.f / fmaxf(sqrtf(sk0), 1e-12f);
    const float rk1 = 1.f / fmaxf(sqrtf(sk1), 1e-12f);
    const float tq = rq * temp[h];
    const long base = (((long)(b*HEADS + h)) * 8) * (HD*HD) + c*HD;
    float s0 = 0.f, s1 = 0.f;
#pragma unroll
    for (int mc = 0; mc < 8; mc++) {
        s0 += part[base + (long)mc*(HD*HD) + lane];
        s1 += part[base + (long)mc*(HD*HD) + lane + 32];
    }
    float v0 = s0 * tq * rk0, v1 = s1 * tq * rk1;
    float mx = fmaxf(v0, v1);
#pragma unroll
    for (int o = 16; o; o >>= 1) mx = fmaxf(mx, __shfl_xor_sync(~0u, mx, o));
    const float e0 = expf(v0 - mx), e1 = expf(v1 - mx);
    float s = e0 + e1;
#pragma unroll
    for (int o = 16; o; o >>= 1) s += __shfl_xor_sync(~0u, s, o);
    const float inv = 1.f / s;
    float* ap = attn + (((long)(b*HEADS + h))*HD + c)*HD;
    ap[lane] = e0 * inv;
    ap[lane + 32] = e1 * inv;
}

// ---------------- W2h = half(w_out @ blockdiag(attn)) ----------------
__global__ void w2_kernel_h(const float* __restrict__ w_out, const float* __restrict__ attn,
                            __half* __restrict__ W2h)
{
    const int b = blockIdx.z, h = blockIdx.y;
    const int tid = threadIdx.x;
    __shared__ float sa[HD*HD];
    const float* ap = attn + ((long)(b*HEADS + h)) * HD * HD;
    for (int i = tid; i < HD*HD; i += 256) sa[i] = ap[i];
    __syncthreads();
    const int o = blockIdx.x * 4 + (tid >> 6);
    const int d = tid & 63;
    const float* wrow = w_out + (long)o * DIM + h * HD;
    float acc = 0.f;
#pragma unroll
    for (int c = 0; c < HD; c++) acc += wrow[c] * sa[c*HD + d];
    W2h[((long)b*DIM + o) * DIM + h*HD + d] = __float2half_rn(acc);
}

// ---------------- launcher ----------------
extern "C" void kernel_launch(void* const* d_in, const int* in_sizes, int n_in,
                              void* d_out, int out_size)
{
    const float* x    = (const float*)d_in[0];
    const float* y    = (const float*)d_in[1];
    const float* temp = (const float*)d_in[2];
    const float* wkv  = (const float*)d_in[3];
    const float* wq   = (const float*)d_in[4];
    const float* wdw  = (const float*)d_in[5];
    const float* wout = (const float*)d_in[6];
    float* out = (float*)d_out;

    float *kv, *q, *part, *nsq, *attn;
    __half *xTh, *yTh, *vTh, *wkvh, *wqTh, *wdwh, *wc2h, *w2h;
    cudaGetSymbolAddress((void**)&kv,   g_kv);
    cudaGetSymbolAddress((void**)&q,    g_q);
    cudaGetSymbolAddress((void**)&part, g_part);
    cudaGetSymbolAddress((void**)&nsq,  g_nsq);
    cudaGetSymbolAddress((void**)&attn, g_attn);
    cudaGetSymbolAddress((void**)&xTh,  g_xTh);
    cudaGetSymbolAddress((void**)&yTh,  g_yTh);
    cudaGetSymbolAddress((void**)&vTh,  g_vTh);
    cudaGetSymbolAddress((void**)&wkvh, g_wkvh);
    cudaGetSymbolAddress((void**)&wqTh, g_wqTh);
    cudaGetSymbolAddress((void**)&wdwh, g_wdwh);
    cudaGetSymbolAddress((void**)&wc2h, g_wc2h);
    cudaGetSymbolAddress((void**)&w2h,  g_w2h);

    cudaFuncSetAttribute(hgemm<0,0>, cudaFuncAttributeMaxDynamicSharedMemorySize, SMEMB);
    cudaFuncSetAttribute(hgemm<0,1>, cudaFuncAttributeMaxDynamicSharedMemorySize, SMEMB);
    cudaFuncSetAttribute(hgemm<0,2>, cudaFuncAttributeMaxDynamicSharedMemorySize, SMEMB);
    cudaFuncSetAttribute(hgemm256, cudaFuncAttributeMaxDynamicSharedMemorySize, SMEMB2);

    // weight prep (fp16)
    conv_h<<<2048, 256>>>(wkv, wkvh, 2*DIM*DIM);
    prep_wdw_h<<<512, 256>>>(wdw, wdwh);
    transpose_h<0><<<dim3(16,16,1), 256>>>(wq, 0L, wqTh, 0L, DIM, DIM);

    // input transposes (fp16)
    transpose_h<0><<<dim3(128,16,BATCH), 256>>>(x, (long)DIM*MLEN, xTh, (long)MLEN*DIM, DIM, MLEN);
    ypad_zero_h<<<dim3(260,BATCH), 256>>>(yTh);
    transpose_h<1><<<dim3(128,16,BATCH), 256>>>(y, (long)DIM*MLEN, yTh, (long)YROWS*DIM, DIM, MLEN);

    // Wc2h[o2][r*512+c] = sum_o wdwh[r][o2][o] * wqTh[c][o]
    hgemm<0,1><<<dim3(4,4,9), 256, SMEMB>>>(
        wdwh, (long)DIM*DIM, wqTh, 0L, wc2h, 512L, KCONV, DIM, DIM, nullptr);

    // kv: k -> fp32 kv[o][m]; v -> fp16 vTh[m][o] (fused transpose epilogue)
    hgemm<0,2><<<dim3(32,8,BATCH), 256, SMEMB>>>(
        wkvh, 0L, xTh, (long)MLEN*DIM, kv, (long)DIM*MLEN, MLEN, 2*DIM, DIM, vTh);

    // q = conv3x3 implicit GEMM (128x256 tile, single wave), fp32 out
    hgemm256<<<dim3(16,4,BATCH), 256, SMEMB2>>>(
        wc2h, yTh, (long)YROWS*DIM, q, (long)DIM*MLEN);

    // attention
    attn_partial_kernel<<<dim3(8,HEADS,BATCH), 256>>>(q, kv, part, nsq);
    softmax_kernel<<<BATCH*HEADS*HD, 32>>>(part, nsq, temp, attn);
    w2_kernel_h<<<dim3(128,HEADS,BATCH), 256>>>(wout, attn, w2h);

    // out = W2 @ v
    hgemm<0,0><<<dim3(32,4,BATCH), 256, SMEMB>>>(
        w2h, (long)DIM*DIM, vTh, (long)MLEN*DIM, out, (long)DIM*MLEN, MLEN, DIM, DIM, nullptr);
}

// round 10
// speedup vs baseline: 1.1575x; 1.1575x over previous
#include <cuda_runtime.h>
#include <cuda_fp16.h>
#include <math.h>
#include <stdint.h>

#define BATCH 4
#define DIM   512
#define MLEN  4096
#define HEADS 8
#define HD    64
#define KCONV 4608
#define YROWS 4356
#define SMEMB 61440   // 3 * (10240 + 10240)

// ---------------- static scratch ----------------
__device__ float  g_kv  [BATCH*DIM*MLEN];       // k (fp32 [o][m])
__device__ float  g_part[BATCH*HEADS*8*HD*HD];
__device__ float  g_nsq [BATCH*HEADS*8*2*HD];
__device__ float  g_attn[BATCH*HEADS*HD*HD];
__device__ __half g_qh  [BATCH*DIM*MLEN];
__device__ __half g_xTh [BATCH*MLEN*DIM];
__device__ __half g_yTh [BATCH*YROWS*DIM];
__device__ __half g_vTh [BATCH*MLEN*DIM];
__device__ __half g_wkvh[2*DIM*DIM];
__device__ __half g_wqTh[DIM*DIM];
__device__ __half g_wdwh[9*DIM*DIM];
__device__ __half g_wc2h[DIM*KCONV];
__device__ __half g_w2h [BATCH*DIM*DIM];

// ---------------- helpers ----------------
__device__ __forceinline__ void cpa16(uint32_t d, const void* s){
    asm volatile("cp.async.cg.shared.global [%0], [%1], 16;" :: "r"(d), "l"(s));
}
#define CP_COMMIT() asm volatile("cp.async.commit_group;")
#define CP_WAIT1()  asm volatile("cp.async.wait_group 1;")

__device__ __forceinline__ void mma16(float& c0, float& c1, float& c2, float& c3,
                                      uint32_t a0, uint32_t a1, uint32_t a2, uint32_t a3,
                                      uint32_t b0, uint32_t b1){
    asm volatile(
        "mma.sync.aligned.m16n8k16.row.col.f32.f16.f16.f32 "
        "{%0,%1,%2,%3}, {%4,%5,%6,%7}, {%8,%9}, {%0,%1,%2,%3};"
        : "+f"(c0), "+f"(c1), "+f"(c2), "+f"(c3)
        : "r"(a0), "r"(a1), "r"(a2), "r"(a3), "r"(b0), "r"(b1));
}
__device__ __forceinline__ void ldsm4(uint32_t& r0, uint32_t& r1, uint32_t& r2, uint32_t& r3,
                                      uint32_t a){
    asm volatile("ldmatrix.sync.aligned.m8n8.x4.shared.b16 {%0,%1,%2,%3}, [%4];"
        : "=r"(r0), "=r"(r1), "=r"(r2), "=r"(r3) : "r"(a));
}

// ============ hgemm: 128x128, BK=32, occ 2 (R7-validated; dense B) ============
// OUTM: 0 fp32 C; 1 fp16 C
template<int OUTM>
__global__ __launch_bounds__(256, 2)
void hgemm(const __half* __restrict__ A, long lA,
           const __half* __restrict__ B, long lB,
           void* __restrict__ Cv, long lC, int ldC,
           int M, int K)
{
    extern __shared__ __half sh[];
    const uint32_t smb = (uint32_t)__cvta_generic_to_shared(sh);
    A += (long)blockIdx.z * lA;
    B += (long)blockIdx.z * lB;
    const int bm = blockIdx.y * 128, bn = blockIdx.x * 128;
    const int tid = threadIdx.x, lane = tid & 31, warp = tid >> 5;
    const int wm = (warp >> 2) * 64, wn = (warp & 3) * 32;
    const int g = lane >> 2, t = lane & 3;
    const int lrow = tid >> 1, lco = (tid & 1) * 16;

    const uint32_t aOff = (uint32_t)((wm + (lane & 15)) * 80 + (lane >> 4) * 16);
    const uint32_t bOff = (uint32_t)((wn + (lane & 7) + ((lane >> 4) << 3)) * 80
                                     + ((lane >> 3) & 1) * 16);

    float acc[4][4][4];
#pragma unroll
    for (int i = 0; i < 4; i++)
#pragma unroll
        for (int j = 0; j < 4; j++)
#pragma unroll
            for (int r = 0; r < 4; r++) acc[i][j][r] = 0.f;

    const int T = K >> 5;

    auto load = [&](int s, int tt){
        const int k0 = tt << 5;
        const uint32_t sb = smb + (uint32_t)s * 20480u;
        const __half* asrc = A + (long)(bm + lrow) * K + k0 + lco;
        const uint32_t adst = sb + (uint32_t)lrow * 80u + (uint32_t)lco * 2u;
        cpa16(adst,       asrc);
        cpa16(adst + 16u, asrc + 8);
        const __half* bsrc = B + (long)(bn + lrow) * K + k0 + lco;
        const uint32_t bdst = sb + 10240u + (uint32_t)lrow * 80u + (uint32_t)lco * 2u;
        cpa16(bdst,       bsrc);
        cpa16(bdst + 16u, bsrc + 8);
    };

    load(0, 0); CP_COMMIT();
    load(1, 1); CP_COMMIT();

    for (int tt = 0; tt < T; tt++) {
        const int s = tt % 3;
        CP_WAIT1();
        __syncthreads();
        if (tt + 2 < T) load((tt + 2) % 3, tt + 2);
        CP_COMMIT();

        const uint32_t sb = smb + (uint32_t)s * 20480u;
#pragma unroll
        for (int ks = 0; ks < 2; ks++) {
            const uint32_t kb = (uint32_t)ks * 32u;
            uint32_t af[4][4], bf[2][4];
#pragma unroll
            for (int mi = 0; mi < 4; mi++)
                ldsm4(af[mi][0], af[mi][1], af[mi][2], af[mi][3],
                      sb + aOff + (uint32_t)mi * 1280u + kb);
            ldsm4(bf[0][0], bf[0][1], bf[0][2], bf[0][3], sb + 10240u + bOff + kb);
            ldsm4(bf[1][0], bf[1][1], bf[1][2], bf[1][3], sb + 10240u + bOff + 1280u + kb);
#pragma unroll
            for (int mi = 0; mi < 4; mi++)
#pragma unroll
                for (int ni = 0; ni < 4; ni++) {
                    const int p = ni >> 1, q2 = (ni & 1) * 2;
                    mma16(acc[mi][ni][0], acc[mi][ni][1], acc[mi][ni][2], acc[mi][ni][3],
                          af[mi][0], af[mi][1], af[mi][2], af[mi][3],
                          bf[p][q2], bf[p][q2 + 1]);
                }
        }
    }

    if (OUTM == 1) {
        __half* C = (__half*)Cv + (long)blockIdx.z * lC;
#pragma unroll
        for (int mi = 0; mi < 4; mi++) {
            const int row0 = bm + wm + mi * 16 + g;
#pragma unroll
            for (int ni = 0; ni < 4; ni++) {
                const int col = bn + wn + ni * 8 + 2 * t;
                *(__half2*)(C + (long)row0 * ldC + col) =
                    __floats2half2_rn(acc[mi][ni][0], acc[mi][ni][1]);
                *(__half2*)(C + (long)(row0 + 8) * ldC + col) =
                    __floats2half2_rn(acc[mi][ni][2], acc[mi][ni][3]);
            }
        }
    } else {
        float* C = (float*)Cv + (long)blockIdx.z * lC;
#pragma unroll
        for (int mi = 0; mi < 4; mi++) {
            const int row0 = bm + wm + mi * 16 + g;
#pragma unroll
            for (int ni = 0; ni < 4; ni++) {
                const int col = bn + wn + ni * 8 + 2 * t;
                *(float2*)(C + (long)row0 * ldC + col) =
                    make_float2(acc[mi][ni][0], acc[mi][ni][1]);
                *(float2*)(C + (long)(row0 + 8) * ldC + col) =
                    make_float2(acc[mi][ni][2], acc[mi][ni][3]);
            }
        }
    }
}

// ============ hgemm_kc: fused kv + conv launch (tail filling) ============
// blockIdx.y < 4  -> conv tile: q(fp16) = wc2h (*) im2col(yTh)    [scheduled first]
// blockIdx.y >= 4 -> kv tile:   k(fp32) / vT(fp16) = wkvh @ xTh
__global__ __launch_bounds__(256, 2)
void hgemm_kc(const __half* __restrict__ wkvh, const __half* __restrict__ xTh,
              float* __restrict__ kvout, __half* __restrict__ vTh,
              const __half* __restrict__ wc2h, const __half* __restrict__ yTh,
              __half* __restrict__ qh)
{
    extern __shared__ __half sh[];
    const uint32_t smb = (uint32_t)__cvta_generic_to_shared(sh);
    const int z = blockIdx.z;
    const bool isConv = blockIdx.y < 4;
    const int bm = (isConv ? blockIdx.y : (blockIdx.y - 4)) * 128;
    const int bn = blockIdx.x * 128;
    const __half* A = isConv ? wc2h : wkvh;
    const __half* B = isConv ? (yTh + (long)z * YROWS * DIM)
                             : (xTh + (long)z * MLEN * DIM);
    const int K = isConv ? KCONV : DIM;

    const int tid = threadIdx.x, lane = tid & 31, warp = tid >> 5;
    const int wm = (warp >> 2) * 64, wn = (warp & 3) * 32;
    const int g = lane >> 2, t = lane & 3;
    const int lrow = tid >> 1, lco = (tid & 1) * 16;
    const int n = bn + lrow, ph = n >> 6, pw = n & 63;

    const uint32_t aOff = (uint32_t)((wm + (lane & 15)) * 80 + (lane >> 4) * 16);
    const uint32_t bOff = (uint32_t)((wn + (lane & 7) + ((lane >> 4) << 3)) * 80
                                     + ((lane >> 3) & 1) * 16);

    float acc[4][4][4];
#pragma unroll
    for (int i = 0; i < 4; i++)
#pragma unroll
        for (int j = 0; j < 4; j++)
#pragma unroll
            for (int r = 0; r < 4; r++) acc[i][j][r] = 0.f;

    const int T = K >> 5;   // 144 conv / 16 kv

    auto load = [&](int s, int tt){
        const int k0 = tt << 5;
        const uint32_t sb = smb + (uint32_t)s * 20480u;
        const __half* asrc = A + (long)(bm + lrow) * K + k0 + lco;
        const uint32_t adst = sb + (uint32_t)lrow * 80u + (uint32_t)lco * 2u;
        cpa16(adst,       asrc);
        cpa16(adst + 16u, asrc + 8);
        const __half* bsrc;
        if (isConv) {
            const int r = k0 >> 9;
            const int dyr = r / 3, dxr = r - 3 * dyr;
            bsrc = B + ((long)((ph + dyr) * 66 + pw + dxr)) * DIM + (k0 & 511) + lco;
        } else {
            bsrc = B + (long)(bn + lrow) * K + k0 + lco;
        }
        const uint32_t bdst = sb + 10240u + (uint32_t)lrow * 80u + (uint32_t)lco * 2u;
        cpa16(bdst,       bsrc);
        cpa16(bdst + 16u, bsrc + 8);
    };

    load(0, 0); CP_COMMIT();
    load(1, 1); CP_COMMIT();

    for (int tt = 0; tt < T; tt++) {
        const int s = tt % 3;
        CP_WAIT1();
        __syncthreads();
        if (tt + 2 < T) load((tt + 2) % 3, tt + 2);
        CP_COMMIT();

        const uint32_t sb = smb + (uint32_t)s * 20480u;
#pragma unroll
        for (int ks = 0; ks < 2; ks++) {
            const uint32_t kb = (uint32_t)ks * 32u;
            uint32_t af[4][4], bf[2][4];
#pragma unroll
            for (int mi = 0; mi < 4; mi++)
                ldsm4(af[mi][0], af[mi][1], af[mi][2], af[mi][3],
                      sb + aOff + (uint32_t)mi * 1280u + kb);
            ldsm4(bf[0][0], bf[0][1], bf[0][2], bf[0][3], sb + 10240u + bOff + kb);
            ldsm4(bf[1][0], bf[1][1], bf[1][2], bf[1][3], sb + 10240u + bOff + 1280u + kb);
#pragma unroll
            for (int mi = 0; mi < 4; mi++)
#pragma unroll
                for (int ni = 0; ni < 4; ni++) {
                    const int p = ni >> 1, q2 = (ni & 1) * 2;
                    mma16(acc[mi][ni][0], acc[mi][ni][1], acc[mi][ni][2], acc[mi][ni][3],
                          af[mi][0], af[mi][1], af[mi][2], af[mi][3],
                          bf[p][q2], bf[p][q2 + 1]);
                }
        }
    }

    if (isConv) {
        // q fp16, [o][m]
        __half* C = qh + (long)z * DIM * MLEN;
#pragma unroll
        for (int mi = 0; mi < 4; mi++) {
            const int row0 = bm + wm + mi * 16 + g;
#pragma unroll
            for (int ni = 0; ni < 4; ni++) {
                const int col = bn + wn + ni * 8 + 2 * t;
                *(__half2*)(C + (long)row0 * MLEN + col) =
                    __floats2half2_rn(acc[mi][ni][0], acc[mi][ni][1]);
                *(__half2*)(C + (long)(row0 + 8) * MLEN + col) =
                    __floats2half2_rn(acc[mi][ni][2], acc[mi][ni][3]);
            }
        }
    } else if (bm < 512) {
        // k fp32, [o][m]
        float* C = kvout + (long)z * DIM * MLEN;
#pragma unroll
        for (int mi = 0; mi < 4; mi++) {
            const int row0 = bm + wm + mi * 16 + g;
#pragma unroll
            for (int ni = 0; ni < 4; ni++) {
                const int col = bn + wn + ni * 8 + 2 * t;
                *(float2*)(C + (long)row0 * MLEN + col) =
                    make_float2(acc[mi][ni][0], acc[mi][ni][1]);
                *(float2*)(C + (long)(row0 + 8) * MLEN + col) =
                    make_float2(acc[mi][ni][2], acc[mi][ni][3]);
            }
        }
    } else {
        // v -> fp16 transposed [m][o] via smem staging
        __syncthreads();
#pragma unroll
        for (int mi = 0; mi < 4; mi++) {
            const int r0 = wm + mi * 16 + g;
#pragma unroll
            for (int ni = 0; ni < 4; ni++) {
                const int c0 = wn + ni * 8 + 2 * t;
                sh[(c0    ) * 136 + r0    ] = __float2half_rn(acc[mi][ni][0]);
                sh[(c0 + 1) * 136 + r0    ] = __float2half_rn(acc[mi][ni][1]);
                sh[(c0    ) * 136 + r0 + 8] = __float2half_rn(acc[mi][ni][2]);
                sh[(c0 + 1) * 136 + r0 + 8] = __float2half_rn(acc[mi][ni][3]);
            }
        }
        __syncthreads();
        __half* vt = vTh + (long)z * MLEN * DIM;
        const int ml = tid >> 1, ho = (tid & 1) * 64;
        __half* dst = vt + (long)(bn + ml) * DIM + (bm - 512) + ho;
        const __half* srcp = sh + ml * 136 + ho;
#pragma unroll
        for (int i = 0; i < 8; i++)
            *(uint4*)(dst + i * 8) = *(const uint4*)(srcp + i * 8);
    }
}

// ---------------- prep / transpose kernels ----------------
__global__ void conv_h(const float* __restrict__ s, __half* __restrict__ d, int n){
    const int i = blockIdx.x * 256 + threadIdx.x;
    if (i < n) d[i] = __float2half_rn(s[i]);
}

template<int PADY>
__global__ void transpose_h(const float* __restrict__ S, long lS,
                            __half* __restrict__ D, long lD, int R, int C)
{
    __shared__ float tle[32][33];
    S += (long)blockIdx.z * lS;
    D += (long)blockIdx.z * lD;
    const int m0 = blockIdx.x * 32, c0 = blockIdx.y * 32;
    const int tx = threadIdx.x & 31, ty = threadIdx.x >> 5;
#pragma unroll
    for (int i = ty; i < 32; i += 8)
        tle[i][tx] = S[(long)(c0 + i) * C + m0 + tx];
    __syncthreads();
    const long prow = PADY ? (long)(m0 + 2 * (m0 >> 6) + 67) : (long)m0;
#pragma unroll
    for (int i = ty; i < 32; i += 8)
        D[(prow + i) * R + c0 + tx] = __float2half_rn(tle[tx][i]);
}

__global__ void ypad_zero_h(__half* __restrict__ yT)
{
    const int idx = blockIdx.x;
    int row;
    if (idx < 66) row = idx;
    else if (idx < 132) row = 65 * 66 + (idx - 66);
    else { const int i = idx - 132; row = (1 + (i >> 1)) * 66 + (i & 1) * 65; }
    uint32_t* p = (uint32_t*)(yT + ((long)blockIdx.y * YROWS + row) * DIM);
    p[threadIdx.x] = 0u;
}

__global__ void prep_wdw_h(const float* __restrict__ wdw, __half* __restrict__ wdwh)
{
    __shared__ float s[KCONV];
    const int o2 = blockIdx.x;
    const float* src = wdw + (long)o2 * KCONV;
    for (int i = threadIdx.x; i < KCONV; i += 256) s[i] = src[i];
    __syncthreads();
    for (int i = threadIdx.x; i < KCONV; i += 256) {
        const int r = i >> 9, o = i & 511;
        wdwh[((long)r * DIM + o2) * DIM + o] = __float2half_rn(s[o * 9 + r]);
    }
}

// ---------------- attention logits + fused sumsq (q fp16, k fp32) ---------
__global__ __launch_bounds__(256)
void attn_partial_kernel(const __half* __restrict__ Q, const float* __restrict__ KV,
                         float* __restrict__ part, float* __restrict__ nsq)
{
    const int mc = blockIdx.x, h = blockIdx.y, b = blockIdx.z;
    const __half* Qp = Q  + ((long)(b * DIM + h * HD)) * MLEN + mc * 512;
    const float* Kp = KV + ((long)(b * DIM + h * HD)) * MLEN + mc * 512;
    __shared__ float sq[32][64];
    __shared__ float sk[32][64];
    const int tid = threadIdx.x, row = tid >> 2, mg = (tid & 3) * 8;
    const int tx = tid & 15, ty = tid >> 4;
    float acc[4][4];
#pragma unroll
    for (int i = 0; i < 4; i++)
#pragma unroll
        for (int j = 0; j < 4; j++) acc[i][j] = 0.f;
    float ssq = 0.f, ssk = 0.f;
    for (int mt = 0; mt < 512; mt += 32) {
        uint4 qa = *(const uint4*)(Qp + (long)row * MLEN + mt + mg);
        const __half2* qh2 = (const __half2*)&qa;
        float2 f0 = __half22float2(qh2[0]);
        float2 f1 = __half22float2(qh2[1]);
        float2 f2 = __half22float2(qh2[2]);
        float2 f3 = __half22float2(qh2[3]);
        sq[mg+0][row]=f0.x; sq[mg+1][row]=f0.y; sq[mg+2][row]=f1.x; sq[mg+3][row]=f1.y;
        sq[mg+4][row]=f2.x; sq[mg+5][row]=f2.y; sq[mg+6][row]=f3.x; sq[mg+7][row]=f3.y;
        ssq += f0.x*f0.x+f0.y*f0.y+f1.x*f1.x+f1.y*f1.y
             + f2.x*f2.x+f2.y*f2.y+f3.x*f3.x+f3.y*f3.y;
        float4 b0 = *(const float4*)(Kp + (long)row * MLEN + mt + mg);
        float4 b1 = *(const float4*)(Kp + (long)row * MLEN + mt + mg + 4);
        sk[mg+0][row]=b0.x; sk[mg+1][row]=b0.y; sk[mg+2][row]=b0.z; sk[mg+3][row]=b0.w;
        sk[mg+4][row]=b1.x; sk[mg+5][row]=b1.y; sk[mg+6][row]=b1.z; sk[mg+7][row]=b1.w;
        ssk += b0.x*b0.x+b0.y*b0.y+b0.z*b0.z+b0.w*b0.w + b1.x*b1.x+b1.y*b1.y+b1.z*b1.z+b1.w*b1.w;
        __syncthreads();
#pragma unroll
        for (int mm = 0; mm < 32; mm++) {
            float ra[4], rb[4];
#pragma unroll
            for (int i = 0; i < 4; i++) ra[i] = sq[mm][ty*4+i];
#pragma unroll
            for (int j = 0; j < 4; j++) rb[j] = sk[mm][tx*4+j];
#pragma unroll
            for (int i = 0; i < 4; i++)
#pragma unroll
                for (int j = 0; j < 4; j++) acc[i][j] += ra[i]*rb[j];
        }
        __syncthreads();
    }
    ssq += __shfl_xor_sync(~0u, ssq, 1); ssq += __shfl_xor_sync(~0u, ssq, 2);
    ssk += __shfl_xor_sync(~0u, ssk, 1); ssk += __shfl_xor_sync(~0u, ssk, 2);
    if ((tid & 3) == 0) {
        const long nb = (((long)(b*HEADS + h))*8 + mc) * 2 * HD;
        nsq[nb + row] = ssq;
        nsq[nb + HD + row] = ssk;
    }
    float* pp = part + ((((long)(b*HEADS + h))*8 + mc)*HD + ty*4)*HD + tx*4;
#pragma unroll
    for (int i = 0; i < 4; i++)
#pragma unroll
        for (int j = 0; j < 4; j++) pp[i*HD + j] = acc[i][j];
}

__global__ void softmax_kernel(const float* __restrict__ part, const float* __restrict__ nsq,
                               const float* __restrict__ temp, float* __restrict__ attn)
{
    const int row = blockIdx.x;
    const int b = row >> 9, h = (row >> 6) & 7, c = row & 63;
    const int lane = threadIdx.x;
    const long nb = ((long)(b*HEADS + h)) * 8 * 2 * HD;
    float sqs = 0.f, sk0 = 0.f, sk1 = 0.f;
#pragma unroll
    for (int mc = 0; mc < 8; mc++) {
        sqs += nsq[nb + mc*2*HD + c];
        sk0 += nsq[nb + mc*2*HD + HD + lane];
        sk1 += nsq[nb + mc*2*HD + HD + lane + 32];
    }
    const float rq  = 1.f / fmaxf(sqrtf(sqs), 1e-12f);
    const float rk0 = 1.f / fmaxf(sqrtf(sk0), 1e-12f);
    const float rk1 = 1.f / fmaxf(sqrtf(sk1), 1e-12f);
    const float tq = rq * temp[h];
    const long base = (((long)(b*HEADS + h)) * 8) * (HD*HD) + c*HD;
    float s0 = 0.f, s1 = 0.f;
#pragma unroll
    for (int mc = 0; mc < 8; mc++) {
        s0 += part[base + (long)mc*(HD*HD) + lane];
        s1 += part[base + (long)mc*(HD*HD) + lane + 32];
    }
    float v0 = s0 * tq * rk0, v1 = s1 * tq * rk1;
    float mx = fmaxf(v0, v1);
#pragma unroll
    for (int o = 16; o; o >>= 1) mx = fmaxf(mx, __shfl_xor_sync(~0u, mx, o));
    const float e0 = expf(v0 - mx), e1 = expf(v1 - mx);
    float s = e0 + e1;
#pragma unroll
    for (int o = 16; o; o >>= 1) s += __shfl_xor_sync(~0u, s, o);
    const float inv = 1.f / s;
    float* ap = attn + (((long)(b*HEADS + h))*HD + c)*HD;
    ap[lane] = e0 * inv;
    ap[lane + 32] = e1 * inv;
}

// ---------------- W2h = half(w_out @ blockdiag(attn)) ----------------
__global__ void w2_kernel_h(const float* __restrict__ w_out, const float* __restrict__ attn,
                            __half* __restrict__ W2h)
{
    const int b = blockIdx.z, h = blockIdx.y;
    const int tid = threadIdx.x;
    __shared__ float sa[HD*HD];
    const float* ap = attn + ((long)(b*HEADS + h)) * HD * HD;
    for (int i = tid; i < HD*HD; i += 256) sa[i] = ap[i];
    __syncthreads();
    const int o = blockIdx.x * 4 + (tid >> 6);
    const int d = tid & 63;
    const float* wrow = w_out + (long)o * DIM + h * HD;
    float acc = 0.f;
#pragma unroll
    for (int c = 0; c < HD; c++) acc += wrow[c] * sa[c*HD + d];
    W2h[((long)b*DIM + o) * DIM + h*HD + d] = __float2half_rn(acc);
}

// ---------------- launcher ----------------
extern "C" void kernel_launch(void* const* d_in, const int* in_sizes, int n_in,
                              void* d_out, int out_size)
{
    const float* x    = (const float*)d_in[0];
    const float* y    = (const float*)d_in[1];
    const float* temp = (const float*)d_in[2];
    const float* wkv  = (const float*)d_in[3];
    const float* wq   = (const float*)d_in[4];
    const float* wdw  = (const float*)d_in[5];
    const float* wout = (const float*)d_in[6];
    float* out = (float*)d_out;

    float *kv, *part, *nsq, *attn;
    __half *qh, *xTh, *yTh, *vTh, *wkvh, *wqTh, *wdwh, *wc2h, *w2h;
    cudaGetSymbolAddress((void**)&kv,   g_kv);
    cudaGetSymbolAddress((void**)&part, g_part);
    cudaGetSymbolAddress((void**)&nsq,  g_nsq);
    cudaGetSymbolAddress((void**)&attn, g_attn);
    cudaGetSymbolAddress((void**)&qh,   g_qh);
    cudaGetSymbolAddress((void**)&xTh,  g_xTh);
    cudaGetSymbolAddress((void**)&yTh,  g_yTh);
    cudaGetSymbolAddress((void**)&vTh,  g_vTh);
    cudaGetSymbolAddress((void**)&wkvh, g_wkvh);
    cudaGetSymbolAddress((void**)&wqTh, g_wqTh);
    cudaGetSymbolAddress((void**)&wdwh, g_wdwh);
    cudaGetSymbolAddress((void**)&wc2h, g_wc2h);
    cudaGetSymbolAddress((void**)&w2h,  g_w2h);

    cudaFuncSetAttribute(hgemm<0>, cudaFuncAttributeMaxDynamicSharedMemorySize, SMEMB);
    cudaFuncSetAttribute(hgemm<1>, cudaFuncAttributeMaxDynamicSharedMemorySize, SMEMB);
    cudaFuncSetAttribute(hgemm_kc, cudaFuncAttributeMaxDynamicSharedMemorySize, SMEMB);

    // weight prep (fp16)
    conv_h<<<2048, 256>>>(wkv, wkvh, 2*DIM*DIM);
    prep_wdw_h<<<512, 256>>>(wdw, wdwh);
    transpose_h<0><<<dim3(16,16,1), 256>>>(wq, 0L, wqTh, 0L, DIM, DIM);

    // input transposes (fp16)
    transpose_h<0><<<dim3(128,16,BATCH), 256>>>(x, (long)DIM*MLEN, xTh, (long)MLEN*DIM, DIM, MLEN);
    ypad_zero_h<<<dim3(260,BATCH), 256>>>(yTh);
    transpose_h<1><<<dim3(128,16,BATCH), 256>>>(y, (long)DIM*MLEN, yTh, (long)YROWS*DIM, DIM, MLEN);

    // Wc2h[o2][r*512+c] = sum_o wdwh[r][o2][o] * wqTh[c][o]
    hgemm<1><<<dim3(4,4,9), 256, SMEMB>>>(
        wdwh, (long)DIM*DIM, wqTh, 0L, wc2h, 512L, KCONV, DIM, DIM);

    // fused: conv (q fp16) + kv (k fp32, vT fp16) in one launch
    hgemm_kc<<<dim3(32,12,BATCH), 256, SMEMB>>>(
        wkvh, xTh, kv, vTh, wc2h, yTh, qh);

    // attention
    attn_partial_kernel<<<dim3(8,HEADS,BATCH), 256>>>(qh, kv, part, nsq);
    softmax_kernel<<<BATCH*HEADS*HD, 32>>>(part, nsq, temp, attn);
    w2_kernel_h<<<dim3(128,HEADS,BATCH), 256>>>(wout, attn, w2h);

    // out = W2 @ v
    hgemm<0><<<dim3(32,4,BATCH), 256, SMEMB>>>(
        w2h, (long)DIM*DIM, vTh, (long)MLEN*DIM, out, (long)DIM*MLEN, MLEN, DIM, DIM);
}

// round 11
// speedup vs baseline: 1.1829x; 1.0220x over previous
#include <cuda_runtime.h>
#include <cuda_fp16.h>
#include <math.h>
#include <stdint.h>

#define BATCH 4
#define DIM   512
#define MLEN  4096
#define HEADS 8
#define HD    64
#define KCONV 4608
#define YROWS 4356
#define SMEMB 61440   // 3 * (10240 + 10240)

// ---------------- static scratch ----------------
__device__ float  g_part[BATCH*HEADS*8*HD*HD];
__device__ float  g_nsq [BATCH*HEADS*8*2*HD];
__device__ float  g_attn[BATCH*HEADS*HD*HD];
__device__ __half g_qh  [BATCH*DIM*MLEN];
__device__ __half g_kh  [BATCH*DIM*MLEN];
__device__ __half g_xTh [BATCH*MLEN*DIM];
__device__ __half g_yTh [BATCH*YROWS*DIM];
__device__ __half g_vTh [BATCH*MLEN*DIM];
__device__ __half g_wkvh[2*DIM*DIM];
__device__ __half g_wqTh[DIM*DIM];
__device__ __half g_wdwh[9*DIM*DIM];
__device__ __half g_wc2h[DIM*KCONV];
__device__ __half g_w2h [BATCH*DIM*DIM];

// ---------------- helpers ----------------
__device__ __forceinline__ void cpa16(uint32_t d, const void* s){
    asm volatile("cp.async.cg.shared.global [%0], [%1], 16;" :: "r"(d), "l"(s));
}
#define CP_COMMIT() asm volatile("cp.async.commit_group;")
#define CP_WAIT1()  asm volatile("cp.async.wait_group 1;")

__device__ __forceinline__ void mma16(float& c0, float& c1, float& c2, float& c3,
                                      uint32_t a0, uint32_t a1, uint32_t a2, uint32_t a3,
                                      uint32_t b0, uint32_t b1){
    asm volatile(
        "mma.sync.aligned.m16n8k16.row.col.f32.f16.f16.f32 "
        "{%0,%1,%2,%3}, {%4,%5,%6,%7}, {%8,%9}, {%0,%1,%2,%3};"
        : "+f"(c0), "+f"(c1), "+f"(c2), "+f"(c3)
        : "r"(a0), "r"(a1), "r"(a2), "r"(a3), "r"(b0), "r"(b1));
}
__device__ __forceinline__ void ldsm4(uint32_t& r0, uint32_t& r1, uint32_t& r2, uint32_t& r3,
                                      uint32_t a){
    asm volatile("ldmatrix.sync.aligned.m8n8.x4.shared.b16 {%0,%1,%2,%3}, [%4];"
        : "=r"(r0), "=r"(r1), "=r"(r2), "=r"(r3) : "r"(a));
}

// ============ hgemm: 128x128, BK=32, occ 2 (R7-validated) ============
// OUTM: 0 fp32 C; 1 fp16 C; 2 kv-special (bm<512 -> fp16 k; else vT fp16)
template<int CONV, int OUTM>
__global__ __launch_bounds__(256, 2)
void hgemm(const __half* __restrict__ A, long lA,
           const __half* __restrict__ B, long lB,
           void* __restrict__ Cv, long lC, int ldC,
           int M, int K, __half* __restrict__ VT)
{
    extern __shared__ __half sh[];
    const uint32_t smb = (uint32_t)__cvta_generic_to_shared(sh);
    A += (long)blockIdx.z * lA;
    B += (long)blockIdx.z * lB;
    const int bm = blockIdx.y * 128, bn = blockIdx.x * 128;
    const int tid = threadIdx.x, lane = tid & 31, warp = tid >> 5;
    const int wm = (warp >> 2) * 64, wn = (warp & 3) * 32;
    const int g = lane >> 2, t = lane & 3;
    const int lrow = tid >> 1, lco = (tid & 1) * 16;

    int ph = 0, pw = 0;
    if (CONV) { const int n = bn + lrow; ph = n >> 6; pw = n & 63; }

    const uint32_t aOff = (uint32_t)((wm + (lane & 15)) * 80 + (lane >> 4) * 16);
    const uint32_t bOff = (uint32_t)((wn + (lane & 7) + ((lane >> 4) << 3)) * 80
                                     + ((lane >> 3) & 1) * 16);

    float acc[4][4][4];
#pragma unroll
    for (int i = 0; i < 4; i++)
#pragma unroll
        for (int j = 0; j < 4; j++)
#pragma unroll
            for (int r = 0; r < 4; r++) acc[i][j][r] = 0.f;

    const int T = K >> 5;

    auto load = [&](int s, int tt){
        const int k0 = tt << 5;
        const uint32_t sb = smb + (uint32_t)s * 20480u;
        const __half* asrc = A + (long)(bm + lrow) * K + k0 + lco;
        const uint32_t adst = sb + (uint32_t)lrow * 80u + (uint32_t)lco * 2u;
        cpa16(adst,       asrc);
        cpa16(adst + 16u, asrc + 8);
        const __half* bsrc;
        if (CONV) {
            const int r = k0 >> 9;
            const int dyr = r / 3, dxr = r - 3 * dyr;
            bsrc = B + ((long)((ph + dyr) * 66 + pw + dxr)) * DIM + (k0 & 511) + lco;
        } else {
            bsrc = B + (long)(bn + lrow) * K + k0 + lco;
        }
        const uint32_t bdst = sb + 10240u + (uint32_t)lrow * 80u + (uint32_t)lco * 2u;
        cpa16(bdst,       bsrc);
        cpa16(bdst + 16u, bsrc + 8);
    };

    load(0, 0); CP_COMMIT();
    load(1, 1); CP_COMMIT();

    for (int tt = 0; tt < T; tt++) {
        const int s = tt % 3;
        CP_WAIT1();
        __syncthreads();
        if (tt + 2 < T) load((tt + 2) % 3, tt + 2);
        CP_COMMIT();

        const uint32_t sb = smb + (uint32_t)s * 20480u;
#pragma unroll
        for (int ks = 0; ks < 2; ks++) {
            const uint32_t kb = (uint32_t)ks * 32u;
            uint32_t af[4][4], bf[2][4];
#pragma unroll
            for (int mi = 0; mi < 4; mi++)
                ldsm4(af[mi][0], af[mi][1], af[mi][2], af[mi][3],
                      sb + aOff + (uint32_t)mi * 1280u + kb);
            ldsm4(bf[0][0], bf[0][1], bf[0][2], bf[0][3], sb + 10240u + bOff + kb);
            ldsm4(bf[1][0], bf[1][1], bf[1][2], bf[1][3], sb + 10240u + bOff + 1280u + kb);
#pragma unroll
            for (int mi = 0; mi < 4; mi++)
#pragma unroll
                for (int ni = 0; ni < 4; ni++) {
                    const int p = ni >> 1, q2 = (ni & 1) * 2;
                    mma16(acc[mi][ni][0], acc[mi][ni][1], acc[mi][ni][2], acc[mi][ni][3],
                          af[mi][0], af[mi][1], af[mi][2], af[mi][3],
                          bf[p][q2], bf[p][q2 + 1]);
                }
        }
    }

    const bool vpath = (OUTM == 2) && (bm >= 512);
    if (OUTM == 1 || (OUTM == 2 && !vpath)) {
        __half* C = (__half*)Cv + (long)blockIdx.z * lC;
#pragma unroll
        for (int mi = 0; mi < 4; mi++) {
            const int row0 = bm + wm + mi * 16 + g;
#pragma unroll
            for (int ni = 0; ni < 4; ni++) {
                const int col = bn + wn + ni * 8 + 2 * t;
                *(__half2*)(C + (long)row0 * ldC + col) =
                    __floats2half2_rn(acc[mi][ni][0], acc[mi][ni][1]);
                *(__half2*)(C + (long)(row0 + 8) * ldC + col) =
                    __floats2half2_rn(acc[mi][ni][2], acc[mi][ni][3]);
            }
        }
    } else if (OUTM == 0) {
        float* C = (float*)Cv + (long)blockIdx.z * lC;
#pragma unroll
        for (int mi = 0; mi < 4; mi++) {
            const int row0 = bm + wm + mi * 16 + g;
#pragma unroll
            for (int ni = 0; ni < 4; ni++) {
                const int col = bn + wn + ni * 8 + 2 * t;
                *(float2*)(C + (long)row0 * ldC + col) =
                    make_float2(acc[mi][ni][0], acc[mi][ni][1]);
                *(float2*)(C + (long)(row0 + 8) * ldC + col) =
                    make_float2(acc[mi][ni][2], acc[mi][ni][3]);
            }
        }
    } else {
        // v -> fp16 transposed [m][o] via smem staging
        __syncthreads();
#pragma unroll
        for (int mi = 0; mi < 4; mi++) {
            const int r0 = wm + mi * 16 + g;
#pragma unroll
            for (int ni = 0; ni < 4; ni++) {
                const int c0 = wn + ni * 8 + 2 * t;
                sh[(c0    ) * 136 + r0    ] = __float2half_rn(acc[mi][ni][0]);
                sh[(c0 + 1) * 136 + r0    ] = __float2half_rn(acc[mi][ni][1]);
                sh[(c0    ) * 136 + r0 + 8] = __float2half_rn(acc[mi][ni][2]);
                sh[(c0 + 1) * 136 + r0 + 8] = __float2half_rn(acc[mi][ni][3]);
            }
        }
        __syncthreads();
        __half* vt = VT + (long)blockIdx.z * MLEN * DIM;
        const int ml = tid >> 1, ho = (tid & 1) * 64;
        __half* dst = vt + (long)(bn + ml) * DIM + (bm - 512) + ho;
        const __half* srcp = sh + ml * 136 + ho;
#pragma unroll
        for (int i = 0; i < 8; i++)
            *(uint4*)(dst + i * 8) = *(const uint4*)(srcp + i * 8);
    }
}

// ---------------- prep / transpose kernels ----------------
__global__ void conv_h(const float* __restrict__ s, __half* __restrict__ d, int n){
    const int i = blockIdx.x * 256 + threadIdx.x;
    if (i < n) d[i] = __float2half_rn(s[i]);
}

template<int PADY>
__global__ void transpose_h(const float* __restrict__ S, long lS,
                            __half* __restrict__ D, long lD, int R, int C)
{
    __shared__ float tle[32][33];
    S += (long)blockIdx.z * lS;
    D += (long)blockIdx.z * lD;
    const int m0 = blockIdx.x * 32, c0 = blockIdx.y * 32;
    const int tx = threadIdx.x & 31, ty = threadIdx.x >> 5;
#pragma unroll
    for (int i = ty; i < 32; i += 8)
        tle[i][tx] = S[(long)(c0 + i) * C + m0 + tx];
    __syncthreads();
    const long prow = PADY ? (long)(m0 + 2 * (m0 >> 6) + 67) : (long)m0;
#pragma unroll
    for (int i = ty; i < 32; i += 8)
        D[(prow + i) * R + c0 + tx] = __float2half_rn(tle[tx][i]);
}

__global__ void ypad_zero_h(__half* __restrict__ yT)
{
    const int idx = blockIdx.x;
    int row;
    if (idx < 66) row = idx;
    else if (idx < 132) row = 65 * 66 + (idx - 66);
    else { const int i = idx - 132; row = (1 + (i >> 1)) * 66 + (i & 1) * 65; }
    uint32_t* p = (uint32_t*)(yT + ((long)blockIdx.y * YROWS + row) * DIM);
    p[threadIdx.x] = 0u;
}

__global__ void prep_wdw_h(const float* __restrict__ wdw, __half* __restrict__ wdwh)
{
    __shared__ float s[KCONV];
    const int o2 = blockIdx.x;
    const float* src = wdw + (long)o2 * KCONV;
    for (int i = threadIdx.x; i < KCONV; i += 256) s[i] = src[i];
    __syncthreads();
    for (int i = threadIdx.x; i < KCONV; i += 256) {
        const int r = i >> 9, o = i & 511;
        wdwh[((long)r * DIM + o2) * DIM + o] = __float2half_rn(s[o * 9 + r]);
    }
}

// ---------------- attention logits + fused sumsq (q,k fp16) ----------------
__global__ __launch_bounds__(256)
void attn_partial_kernel(const __half* __restrict__ Q, const __half* __restrict__ KV,
                         float* __restrict__ part, float* __restrict__ nsq)
{
    const int mc = blockIdx.x, h = blockIdx.y, b = blockIdx.z;
    const __half* Qp = Q  + ((long)(b * DIM + h * HD)) * MLEN + mc * 512;
    const __half* Kp = KV + ((long)(b * DIM + h * HD)) * MLEN + mc * 512;
    __shared__ float sq[32][64];
    __shared__ float sk[32][64];
    const int tid = threadIdx.x, row = tid >> 2, mg = (tid & 3) * 8;
    const int tx = tid & 15, ty = tid >> 4;
    float acc[4][4];
#pragma unroll
    for (int i = 0; i < 4; i++)
#pragma unroll
        for (int j = 0; j < 4; j++) acc[i][j] = 0.f;
    float ssq = 0.f, ssk = 0.f;
    for (int mt = 0; mt < 512; mt += 32) {
        uint4 qa = *(const uint4*)(Qp + (long)row * MLEN + mt + mg);
        const __half2* qh2 = (const __half2*)&qa;
        float2 f0 = __half22float2(qh2[0]);
        float2 f1 = __half22float2(qh2[1]);
        float2 f2 = __half22float2(qh2[2]);
        float2 f3 = __half22float2(qh2[3]);
        sq[mg+0][row]=f0.x; sq[mg+1][row]=f0.y; sq[mg+2][row]=f1.x; sq[mg+3][row]=f1.y;
        sq[mg+4][row]=f2.x; sq[mg+5][row]=f2.y; sq[mg+6][row]=f3.x; sq[mg+7][row]=f3.y;
        ssq += f0.x*f0.x+f0.y*f0.y+f1.x*f1.x+f1.y*f1.y
             + f2.x*f2.x+f2.y*f2.y+f3.x*f3.x+f3.y*f3.y;
        uint4 ka = *(const uint4*)(Kp + (long)row * MLEN + mt + mg);
        const __half2* kh2 = (const __half2*)&ka;
        float2 g0 = __half22float2(kh2[0]);
        float2 g1 = __half22float2(kh2[1]);
        float2 g2 = __half22float2(kh2[2]);
        float2 g3 = __half22float2(kh2[3]);
        sk[mg+0][row]=g0.x; sk[mg+1][row]=g0.y; sk[mg+2][row]=g1.x; sk[mg+3][row]=g1.y;
        sk[mg+4][row]=g2.x; sk[mg+5][row]=g2.y; sk[mg+6][row]=g3.x; sk[mg+7][row]=g3.y;
        ssk += g0.x*g0.x+g0.y*g0.y+g1.x*g1.x+g1.y*g1.y
             + g2.x*g2.x+g2.y*g2.y+g3.x*g3.x+g3.y*g3.y;
        __syncthreads();
#pragma unroll
        for (int mm = 0; mm < 32; mm++) {
            float ra[4], rb[4];
#pragma unroll
            for (int i = 0; i < 4; i++) ra[i] = sq[mm][ty*4+i];
#pragma unroll
            for (int j = 0; j < 4; j++) rb[j] = sk[mm][tx*4+j];
#pragma unroll
            for (int i = 0; i < 4; i++)
#pragma unroll
                for (int j = 0; j < 4; j++) acc[i][j] += ra[i]*rb[j];
        }
        __syncthreads();
    }
    ssq += __shfl_xor_sync(~0u, ssq, 1); ssq += __shfl_xor_sync(~0u, ssq, 2);
    ssk += __shfl_xor_sync(~0u, ssk, 1); ssk += __shfl_xor_sync(~0u, ssk, 2);
    if ((tid & 3) == 0) {
        const long nb = (((long)(b*HEADS + h))*8 + mc) * 2 * HD;
        nsq[nb + row] = ssq;
        nsq[nb + HD + row] = ssk;
    }
    float* pp = part + ((((long)(b*HEADS + h))*8 + mc)*HD + ty*4)*HD + tx*4;
#pragma unroll
    for (int i = 0; i < 4; i++)
#pragma unroll
        for (int j = 0; j < 4; j++) pp[i*HD + j] = acc[i][j];
}

__global__ void softmax_kernel(const float* __restrict__ part, const float* __restrict__ nsq,
                               const float* __restrict__ temp, float* __restrict__ attn)
{
    const int row = blockIdx.x;
    const int b = row >> 9, h = (row >> 6) & 7, c = row & 63;
    const int lane = threadIdx.x;
    const long nb = ((long)(b*HEADS + h)) * 8 * 2 * HD;
    float sqs = 0.f, sk0 = 0.f, sk1 = 0.f;
#pragma unroll
    for (int mc = 0; mc < 8; mc++) {
        sqs += nsq[nb + mc*2*HD + c];
        sk0 += nsq[nb + mc*2*HD + HD + lane];
        sk1 += nsq[nb + mc*2*HD + HD + lane + 32];
    }
    const float rq  = 1.f / fmaxf(sqrtf(sqs), 1e-12f);
    const float rk0 = 1.f / fmaxf(sqrtf(sk0), 1e-12f);
    const float rk1 = 1.f / fmaxf(sqrtf(sk1), 1e-12f);
    const float tq = rq * temp[h];
    const long base = (((long)(b*HEADS + h)) * 8) * (HD*HD) + c*HD;
    float s0 = 0.f, s1 = 0.f;
#pragma unroll
    for (int mc = 0; mc < 8; mc++) {
        s0 += part[base + (long)mc*(HD*HD) + lane];
        s1 += part[base + (long)mc*(HD*HD) + lane + 32];
    }
    float v0 = s0 * tq * rk0, v1 = s1 * tq * rk1;
    float mx = fmaxf(v0, v1);
#pragma unroll
    for (int o = 16; o; o >>= 1) mx = fmaxf(mx, __shfl_xor_sync(~0u, mx, o));
    const float e0 = expf(v0 - mx), e1 = expf(v1 - mx);
    float s = e0 + e1;
#pragma unroll
    for (int o = 16; o; o >>= 1) s += __shfl_xor_sync(~0u, s, o);
    const float inv = 1.f / s;
    float* ap = attn + (((long)(b*HEADS + h))*HD + c)*HD;
    ap[lane] = e0 * inv;
    ap[lane + 32] = e1 * inv;
}

// ---------------- W2h = half(w_out @ blockdiag(attn)) ----------------
__global__ void w2_kernel_h(const float* __restrict__ w_out, const float* __restrict__ attn,
                            __half* __restrict__ W2h)
{
    const int b = blockIdx.z, h = blockIdx.y;
    const int tid = threadIdx.x;
    __shared__ float sa[HD*HD];
    const float* ap = attn + ((long)(b*HEADS + h)) * HD * HD;
    for (int i = tid; i < HD*HD; i += 256) sa[i] = ap[i];
    __syncthreads();
    const int o = blockIdx.x * 4 + (tid >> 6);
    const int d = tid & 63;
    const float* wrow = w_out + (long)o * DIM + h * HD;
    float acc = 0.f;
#pragma unroll
    for (int c = 0; c < HD; c++) acc += wrow[c] * sa[c*HD + d];
    W2h[((long)b*DIM + o) * DIM + h*HD + d] = __float2half_rn(acc);
}

// ---------------- launcher ----------------
extern "C" void kernel_launch(void* const* d_in, const int* in_sizes, int n_in,
                              void* d_out, int out_size)
{
    const float* x    = (const float*)d_in[0];
    const float* y    = (const float*)d_in[1];
    const float* temp = (const float*)d_in[2];
    const float* wkv  = (const float*)d_in[3];
    const float* wq   = (const float*)d_in[4];
    const float* wdw  = (const float*)d_in[5];
    const float* wout = (const float*)d_in[6];
    float* out = (float*)d_out;

    float *part, *nsq, *attn;
    __half *qh, *kh, *xTh, *yTh, *vTh, *wkvh, *wqTh, *wdwh, *wc2h, *w2h;
    cudaGetSymbolAddress((void**)&part, g_part);
    cudaGetSymbolAddress((void**)&nsq,  g_nsq);
    cudaGetSymbolAddress((void**)&attn, g_attn);
    cudaGetSymbolAddress((void**)&qh,   g_qh);
    cudaGetSymbolAddress((void**)&kh,   g_kh);
    cudaGetSymbolAddress((void**)&xTh,  g_xTh);
    cudaGetSymbolAddress((void**)&yTh,  g_yTh);
    cudaGetSymbolAddress((void**)&vTh,  g_vTh);
    cudaGetSymbolAddress((void**)&wkvh, g_wkvh);
    cudaGetSymbolAddress((void**)&wqTh, g_wqTh);
    cudaGetSymbolAddress((void**)&wdwh, g_wdwh);
    cudaGetSymbolAddress((void**)&wc2h, g_wc2h);
    cudaGetSymbolAddress((void**)&w2h,  g_w2h);

    cudaFuncSetAttribute(hgemm<0,0>, cudaFuncAttributeMaxDynamicSharedMemorySize, SMEMB);
    cudaFuncSetAttribute(hgemm<0,1>, cudaFuncAttributeMaxDynamicSharedMemorySize, SMEMB);
    cudaFuncSetAttribute(hgemm<0,2>, cudaFuncAttributeMaxDynamicSharedMemorySize, SMEMB);
    cudaFuncSetAttribute(hgemm<1,1>, cudaFuncAttributeMaxDynamicSharedMemorySize, SMEMB);

    // weight prep (fp16)
    conv_h<<<2048, 256>>>(wkv, wkvh, 2*DIM*DIM);
    prep_wdw_h<<<512, 256>>>(wdw, wdwh);
    transpose_h<0><<<dim3(16,16,1), 256>>>(wq, 0L, wqTh, 0L, DIM, DIM);

    // input transposes (fp16)
    transpose_h<0><<<dim3(128,16,BATCH), 256>>>(x, (long)DIM*MLEN, xTh, (long)MLEN*DIM, DIM, MLEN);
    ypad_zero_h<<<dim3(260,BATCH), 256>>>(yTh);
    transpose_h<1><<<dim3(128,16,BATCH), 256>>>(y, (long)DIM*MLEN, yTh, (long)YROWS*DIM, DIM, MLEN);

    // Wc2h[o2][r*512+c] = sum_o wdwh[r][o2][o] * wqTh[c][o]
    hgemm<0,1><<<dim3(4,4,9), 256, SMEMB>>>(
        wdwh, (long)DIM*DIM, wqTh, 0L, wc2h, 512L, KCONV, DIM, DIM, nullptr);

    // kv: k -> fp16 kh[o][m]; v -> fp16 vTh[m][o] (fused transpose epilogue)
    hgemm<0,2><<<dim3(32,8,BATCH), 256, SMEMB>>>(
        wkvh, 0L, xTh, (long)MLEN*DIM, kh, (long)DIM*MLEN, MLEN, 2*DIM, DIM, vTh);

    // q = conv3x3 implicit GEMM, fp16 out
    hgemm<1,1><<<dim3(32,4,BATCH), 256, SMEMB>>>(
        wc2h, 0L, yTh, (long)YROWS*DIM, qh, (long)DIM*MLEN, MLEN, DIM, KCONV, nullptr);

    // attention
    attn_partial_kernel<<<dim3(8,HEADS,BATCH), 256>>>(qh, kh, part, nsq);
    softmax_kernel<<<BATCH*HEADS*HD, 32>>>(part, nsq, temp, attn);
    w2_kernel_h<<<dim3(128,HEADS,BATCH), 256>>>(wout, attn, w2h);

    // out = W2 @ v
    hgemm<0,0><<<dim3(32,4,BATCH), 256, SMEMB>>>(
        w2h, (long)DIM*DIM, vTh, (long)MLEN*DIM, out, (long)DIM*MLEN, MLEN, DIM, DIM, nullptr);
}

// round 12
// speedup vs baseline: 1.2531x; 1.0593x over previous
#include <cuda_runtime.h>
#include <cuda_fp16.h>
#include <math.h>
#include <stdint.h>

#define BATCH 4
#define DIM   512
#define MLEN  4096
#define HEADS 8
#define HD    64
#define KCONV 4608
#define YROWS 4356
#define SMEMB 61440   // 3 * (10240 + 10240)
#define ASMEM 30720   // attn: 3 * (5120 + 5120)

// ---------------- static scratch ----------------
__device__ float  g_part[BATCH*HEADS*8*HD*HD];
__device__ float  g_ns2 [BATCH*2*DIM];
__device__ float  g_attn[BATCH*HEADS*HD*HD];
__device__ __half g_qh  [BATCH*DIM*MLEN];
__device__ __half g_kh  [BATCH*DIM*MLEN];
__device__ __half g_xTh [BATCH*MLEN*DIM];
__device__ __half g_yTh [BATCH*YROWS*DIM];
__device__ __half g_vTh [BATCH*MLEN*DIM];
__device__ __half g_wkvh[2*DIM*DIM];
__device__ __half g_wqTh[DIM*DIM];
__device__ __half g_wdwh[9*DIM*DIM];
__device__ __half g_wc2h[DIM*KCONV];
__device__ __half g_w2h [BATCH*DIM*DIM];

// ---------------- helpers ----------------
__device__ __forceinline__ void cpa16(uint32_t d, const void* s){
    asm volatile("cp.async.cg.shared.global [%0], [%1], 16;" :: "r"(d), "l"(s));
}
#define CP_COMMIT() asm volatile("cp.async.commit_group;")
#define CP_WAIT1()  asm volatile("cp.async.wait_group 1;")

__device__ __forceinline__ void mma16(float& c0, float& c1, float& c2, float& c3,
                                      uint32_t a0, uint32_t a1, uint32_t a2, uint32_t a3,
                                      uint32_t b0, uint32_t b1){
    asm volatile(
        "mma.sync.aligned.m16n8k16.row.col.f32.f16.f16.f32 "
        "{%0,%1,%2,%3}, {%4,%5,%6,%7}, {%8,%9}, {%0,%1,%2,%3};"
        : "+f"(c0), "+f"(c1), "+f"(c2), "+f"(c3)
        : "r"(a0), "r"(a1), "r"(a2), "r"(a3), "r"(b0), "r"(b1));
}
__device__ __forceinline__ void ldsm4(uint32_t& r0, uint32_t& r1, uint32_t& r2, uint32_t& r3,
                                      uint32_t a){
    asm volatile("ldmatrix.sync.aligned.m8n8.x4.shared.b16 {%0,%1,%2,%3}, [%4];"
        : "=r"(r0), "=r"(r1), "=r"(r2), "=r"(r3) : "r"(a));
}

// ============ hgemm: 128x128, BK=32, occ 2 (R7/R11-validated) ============
// OUTM: 0 fp32 C; 1 fp16 C; 2 kv-special (bm<512 -> fp16 k; else vT fp16)
template<int CONV, int OUTM>
__global__ __launch_bounds__(256, 2)
void hgemm(const __half* __restrict__ A, long lA,
           const __half* __restrict__ B, long lB,
           void* __restrict__ Cv, long lC, int ldC,
           int M, int K, __half* __restrict__ VT)
{
    extern __shared__ __half sh[];
    const uint32_t smb = (uint32_t)__cvta_generic_to_shared(sh);
    A += (long)blockIdx.z * lA;
    B += (long)blockIdx.z * lB;
    const int bm = blockIdx.y * 128, bn = blockIdx.x * 128;
    const int tid = threadIdx.x, lane = tid & 31, warp = tid >> 5;
    const int wm = (warp >> 2) * 64, wn = (warp & 3) * 32;
    const int g = lane >> 2, t = lane & 3;
    const int lrow = tid >> 1, lco = (tid & 1) * 16;

    int ph = 0, pw = 0;
    if (CONV) { const int n = bn + lrow; ph = n >> 6; pw = n & 63; }

    const uint32_t aOff = (uint32_t)((wm + (lane & 15)) * 80 + (lane >> 4) * 16);
    const uint32_t bOff = (uint32_t)((wn + (lane & 7) + ((lane >> 4) << 3)) * 80
                                     + ((lane >> 3) & 1) * 16);

    float acc[4][4][4];
#pragma unroll
    for (int i = 0; i < 4; i++)
#pragma unroll
        for (int j = 0; j < 4; j++)
#pragma unroll
            for (int r = 0; r < 4; r++) acc[i][j][r] = 0.f;

    const int T = K >> 5;

    auto load = [&](int s, int tt){
        const int k0 = tt << 5;
        const uint32_t sb = smb + (uint32_t)s * 20480u;
        const __half* asrc = A + (long)(bm + lrow) * K + k0 + lco;
        const uint32_t adst = sb + (uint32_t)lrow * 80u + (uint32_t)lco * 2u;
        cpa16(adst,       asrc);
        cpa16(adst + 16u, asrc + 8);
        const __half* bsrc;
        if (CONV) {
            const int r = k0 >> 9;
            const int dyr = r / 3, dxr = r - 3 * dyr;
            bsrc = B + ((long)((ph + dyr) * 66 + pw + dxr)) * DIM + (k0 & 511) + lco;
        } else {
            bsrc = B + (long)(bn + lrow) * K + k0 + lco;
        }
        const uint32_t bdst = sb + 10240u + (uint32_t)lrow * 80u + (uint32_t)lco * 2u;
        cpa16(bdst,       bsrc);
        cpa16(bdst + 16u, bsrc + 8);
    };

    load(0, 0); CP_COMMIT();
    load(1, 1); CP_COMMIT();

    for (int tt = 0; tt < T; tt++) {
        const int s = tt % 3;
        CP_WAIT1();
        __syncthreads();
        if (tt + 2 < T) load((tt + 2) % 3, tt + 2);
        CP_COMMIT();

        const uint32_t sb = smb + (uint32_t)s * 20480u;
#pragma unroll
        for (int ks = 0; ks < 2; ks++) {
            const uint32_t kb = (uint32_t)ks * 32u;
            uint32_t af[4][4], bf[2][4];
#pragma unroll
            for (int mi = 0; mi < 4; mi++)
                ldsm4(af[mi][0], af[mi][1], af[mi][2], af[mi][3],
                      sb + aOff + (uint32_t)mi * 1280u + kb);
            ldsm4(bf[0][0], bf[0][1], bf[0][2], bf[0][3], sb + 10240u + bOff + kb);
            ldsm4(bf[1][0], bf[1][1], bf[1][2], bf[1][3], sb + 10240u + bOff + 1280u + kb);
#pragma unroll
            for (int mi = 0; mi < 4; mi++)
#pragma unroll
                for (int ni = 0; ni < 4; ni++) {
                    const int p = ni >> 1, q2 = (ni & 1) * 2;
                    mma16(acc[mi][ni][0], acc[mi][ni][1], acc[mi][ni][2], acc[mi][ni][3],
                          af[mi][0], af[mi][1], af[mi][2], af[mi][3],
                          bf[p][q2], bf[p][q2 + 1]);
                }
        }
    }

    const bool vpath = (OUTM == 2) && (bm >= 512);
    if (OUTM == 1 || (OUTM == 2 && !vpath)) {
        __half* C = (__half*)Cv + (long)blockIdx.z * lC;
#pragma unroll
        for (int mi = 0; mi < 4; mi++) {
            const int row0 = bm + wm + mi * 16 + g;
#pragma unroll
            for (int ni = 0; ni < 4; ni++) {
                const int col = bn + wn + ni * 8 + 2 * t;
                *(__half2*)(C + (long)row0 * ldC + col) =
                    __floats2half2_rn(acc[mi][ni][0], acc[mi][ni][1]);
                *(__half2*)(C + (long)(row0 + 8) * ldC + col) =
                    __floats2half2_rn(acc[mi][ni][2], acc[mi][ni][3]);
            }
        }
    } else if (OUTM == 0) {
        float* C = (float*)Cv + (long)blockIdx.z * lC;
#pragma unroll
        for (int mi = 0; mi < 4; mi++) {
            const int row0 = bm + wm + mi * 16 + g;
#pragma unroll
            for (int ni = 0; ni < 4; ni++) {
                const int col = bn + wn + ni * 8 + 2 * t;
                *(float2*)(C + (long)row0 * ldC + col) =
                    make_float2(acc[mi][ni][0], acc[mi][ni][1]);
                *(float2*)(C + (long)(row0 + 8) * ldC + col) =
                    make_float2(acc[mi][ni][2], acc[mi][ni][3]);
            }
        }
    } else {
        __syncthreads();
#pragma unroll
        for (int mi = 0; mi < 4; mi++) {
            const int r0 = wm + mi * 16 + g;
#pragma unroll
            for (int ni = 0; ni < 4; ni++) {
                const int c0 = wn + ni * 8 + 2 * t;
                sh[(c0    ) * 136 + r0    ] = __float2half_rn(acc[mi][ni][0]);
                sh[(c0 + 1) * 136 + r0    ] = __float2half_rn(acc[mi][ni][1]);
                sh[(c0    ) * 136 + r0 + 8] = __float2half_rn(acc[mi][ni][2]);
                sh[(c0 + 1) * 136 + r0 + 8] = __float2half_rn(acc[mi][ni][3]);
            }
        }
        __syncthreads();
        __half* vt = VT + (long)blockIdx.z * MLEN * DIM;
        const int ml = tid >> 1, ho = (tid & 1) * 64;
        __half* dst = vt + (long)(bn + ml) * DIM + (bm - 512) + ho;
        const __half* srcp = sh + ml * 136 + ho;
#pragma unroll
        for (int i = 0; i < 8; i++)
            *(uint4*)(dst + i * 8) = *(const uint4*)(srcp + i * 8);
    }
}

// ============ attn_mma2: logits on HMMA, hgemm-pattern at 64x64xK=512 ======
// grid (8, HEADS, BATCH); 8 warps = 4(m) x 2(n); warp tile 16x32, full K.
__global__ __launch_bounds__(256, 2)
void attn_mma2(const __half* __restrict__ qh, const __half* __restrict__ kh,
               float* __restrict__ part)
{
    extern __shared__ __half sh[];
    const uint32_t smb = (uint32_t)__cvta_generic_to_shared(sh);
    const int mc = blockIdx.x, h = blockIdx.y, b = blockIdx.z;
    const __half* Qp = qh + ((long)(b * DIM + h * HD)) * MLEN + mc * 512;
    const __half* Kp = kh + ((long)(b * DIM + h * HD)) * MLEN + mc * 512;
    const int tid = threadIdx.x, lane = tid & 31, warp = tid >> 5;
    const int wm = (warp >> 1) * 16, wn = (warp & 1) * 32;
    const int g = lane >> 2, t = lane & 3;
    const int lrow = tid >> 2, lco = (tid & 3) * 8;   // 64 rows x 32 halves

    const uint32_t aOff = (uint32_t)((wm + (lane & 15)) * 80 + (lane >> 4) * 16);
    const uint32_t bOff = 5120u + (uint32_t)((wn + (lane & 7) + ((lane >> 4) << 3)) * 80
                                             + ((lane >> 3) & 1) * 16);

    float acc[4][4];
#pragma unroll
    for (int j = 0; j < 4; j++)
#pragma unroll
        for (int r = 0; r < 4; r++) acc[j][r] = 0.f;

    const int T = 16;   // 512 / 32

    auto load = [&](int s, int tt){
        const int k0 = tt << 5;
        const uint32_t sb = smb + (uint32_t)s * 10240u;
        cpa16(sb + (uint32_t)lrow * 80u + (uint32_t)lco * 2u,
              Qp + (long)lrow * MLEN + k0 + lco);
        cpa16(sb + 5120u + (uint32_t)lrow * 80u + (uint32_t)lco * 2u,
              Kp + (long)lrow * MLEN + k0 + lco);
    };

    load(0, 0); CP_COMMIT();
    load(1, 1); CP_COMMIT();

    for (int tt = 0; tt < T; tt++) {
        const int s = tt % 3;
        CP_WAIT1();
        __syncthreads();
        if (tt + 2 < T) load((tt + 2) % 3, tt + 2);
        CP_COMMIT();

        const uint32_t sb = smb + (uint32_t)s * 10240u;
#pragma unroll
        for (int ks = 0; ks < 2; ks++) {
            const uint32_t kb = (uint32_t)ks * 32u;
            uint32_t af[4], bf[2][4];
            ldsm4(af[0], af[1], af[2], af[3], sb + aOff + kb);
            ldsm4(bf[0][0], bf[0][1], bf[0][2], bf[0][3], sb + bOff + kb);
            ldsm4(bf[1][0], bf[1][1], bf[1][2], bf[1][3], sb + bOff + 1280u + kb);
#pragma unroll
            for (int ni = 0; ni < 4; ni++) {
                const int p = ni >> 1, q2 = (ni & 1) * 2;
                mma16(acc[ni][0], acc[ni][1], acc[ni][2], acc[ni][3],
                      af[0], af[1], af[2], af[3],
                      bf[p][q2], bf[p][q2 + 1]);
            }
        }
    }

    float* pp = part + (((long)(b * HEADS + h)) * 8 + mc) * 4096;
    const int row0 = wm + g;
#pragma unroll
    for (int ni = 0; ni < 4; ni++) {
        const int col = wn + ni * 8 + 2 * t;
        *(float2*)(pp + row0 * 64 + col)       = make_float2(acc[ni][0], acc[ni][1]);
        *(float2*)(pp + (row0 + 8) * 64 + col) = make_float2(acc[ni][2], acc[ni][3]);
    }
}

// ============ row sumsq over fp16 q/k ============
__global__ void nsq_kernel(const __half* __restrict__ qh, const __half* __restrict__ kh,
                           float* __restrict__ ns2)
{
    const int w = threadIdx.x >> 5, lane = threadIdx.x & 31;
    const int gid = blockIdx.x * 8 + w;            // 0..4095
    const int isK = gid >= BATCH * DIM;
    const int r = gid & (BATCH * DIM - 1);
    const int b = r >> 9, o = r & 511;
    const __half* src = (isK ? kh : qh) + ((long)(b * DIM + o)) * MLEN;
    float ss = 0.f;
#pragma unroll
    for (int i = 0; i < 16; i++) {
        uint4 v = *(const uint4*)(src + i * 256 + lane * 8);
        const __half2* h2 = (const __half2*)&v;
#pragma unroll
        for (int j = 0; j < 4; j++) {
            float2 f = __half22float2(h2[j]);
            ss += f.x * f.x + f.y * f.y;
        }
    }
#pragma unroll
    for (int o2 = 16; o2; o2 >>= 1) ss += __shfl_xor_sync(~0u, ss, o2);
    if (lane == 0) ns2[b * 1024 + isK * 512 + o] = ss;
}

// ---------------- prep / transpose kernels ----------------
__global__ void conv_h(const float* __restrict__ s, __half* __restrict__ d, int n){
    const int i = blockIdx.x * 256 + threadIdx.x;
    if (i < n) d[i] = __float2half_rn(s[i]);
}

template<int PADY>
__global__ void transpose_h(const float* __restrict__ S, long lS,
                            __half* __restrict__ D, long lD, int R, int C)
{
    __shared__ float tle[32][33];
    S += (long)blockIdx.z * lS;
    D += (long)blockIdx.z * lD;
    const int m0 = blockIdx.x * 32, c0 = blockIdx.y * 32;
    const int tx = threadIdx.x & 31, ty = threadIdx.x >> 5;
#pragma unroll
    for (int i = ty; i < 32; i += 8)
        tle[i][tx] = S[(long)(c0 + i) * C + m0 + tx];
    __syncthreads();
    const long prow = PADY ? (long)(m0 + 2 * (m0 >> 6) + 67) : (long)m0;
#pragma unroll
    for (int i = ty; i < 32; i += 8)
        D[(prow + i) * R + c0 + tx] = __float2half_rn(tle[tx][i]);
}

__global__ void ypad_zero_h(__half* __restrict__ yT)
{
    const int idx = blockIdx.x;
    int row;
    if (idx < 66) row = idx;
    else if (idx < 132) row = 65 * 66 + (idx - 66);
    else { const int i = idx - 132; row = (1 + (i >> 1)) * 66 + (i & 1) * 65; }
    uint32_t* p = (uint32_t*)(yT + ((long)blockIdx.y * YROWS + row) * DIM);
    p[threadIdx.x] = 0u;
}

__global__ void prep_wdw_h(const float* __restrict__ wdw, __half* __restrict__ wdwh)
{
    __shared__ float s[KCONV];
    const int o2 = blockIdx.x;
    const float* src = wdw + (long)o2 * KCONV;
    for (int i = threadIdx.x; i < KCONV; i += 256) s[i] = src[i];
    __syncthreads();
    for (int i = threadIdx.x; i < KCONV; i += 256) {
        const int r = i >> 9, o = i & 511;
        wdwh[((long)r * DIM + o2) * DIM + o] = __float2half_rn(s[o * 9 + r]);
    }
}

__global__ void softmax_kernel(const float* __restrict__ part, const float* __restrict__ ns2,
                               const float* __restrict__ temp, float* __restrict__ attn)
{
    const int row = blockIdx.x;
    const int b = row >> 9, h = (row >> 6) & 7, c = row & 63;
    const int lane = threadIdx.x;
    const float sqs = ns2[b * 1024 + h * HD + c];
    const float sk0 = ns2[b * 1024 + 512 + h * HD + lane];
    const float sk1 = ns2[b * 1024 + 512 + h * HD + lane + 32];
    const float rq  = 1.f / fmaxf(sqrtf(sqs), 1e-12f);
    const float rk0 = 1.f / fmaxf(sqrtf(sk0), 1e-12f);
    const float rk1 = 1.f / fmaxf(sqrtf(sk1), 1e-12f);
    const float tq = rq * temp[h];
    const long base = (((long)(b*HEADS + h)) * 8) * (HD*HD) + c*HD;
    float s0 = 0.f, s1 = 0.f;
#pragma unroll
    for (int mc = 0; mc < 8; mc++) {
        s0 += part[base + (long)mc*(HD*HD) + lane];
        s1 += part[base + (long)mc*(HD*HD) + lane + 32];
    }
    float v0 = s0 * tq * rk0, v1 = s1 * tq * rk1;
    float mx = fmaxf(v0, v1);
#pragma unroll
    for (int o = 16; o; o >>= 1) mx = fmaxf(mx, __shfl_xor_sync(~0u, mx, o));
    const float e0 = expf(v0 - mx), e1 = expf(v1 - mx);
    float s = e0 + e1;
#pragma unroll
    for (int o = 16; o; o >>= 1) s += __shfl_xor_sync(~0u, s, o);
    const float inv = 1.f / s;
    float* ap = attn + (((long)(b*HEADS + h))*HD + c)*HD;
    ap[lane] = e0 * inv;
    ap[lane + 32] = e1 * inv;
}

__global__ void w2_kernel_h(const float* __restrict__ w_out, const float* __restrict__ attn,
                            __half* __restrict__ W2h)
{
    const int b = blockIdx.z, h = blockIdx.y;
    const int tid = threadIdx.x;
    __shared__ float sa[HD*HD];
    const float* ap = attn + ((long)(b*HEADS + h)) * HD * HD;
    for (int i = tid; i < HD*HD; i += 256) sa[i] = ap[i];
    __syncthreads();
    const int o = blockIdx.x * 4 + (tid >> 6);
    const int d = tid & 63;
    const float* wrow = w_out + (long)o * DIM + h * HD;
    float acc = 0.f;
#pragma unroll
    for (int c = 0; c < HD; c++) acc += wrow[c] * sa[c*HD + d];
    W2h[((long)b*DIM + o) * DIM + h*HD + d] = __float2half_rn(acc);
}

// ---------------- launcher ----------------
extern "C" void kernel_launch(void* const* d_in, const int* in_sizes, int n_in,
                              void* d_out, int out_size)
{
    const float* x    = (const float*)d_in[0];
    const float* y    = (const float*)d_in[1];
    const float* temp = (const float*)d_in[2];
    const float* wkv  = (const float*)d_in[3];
    const float* wq   = (const float*)d_in[4];
    const float* wdw  = (const float*)d_in[5];
    const float* wout = (const float*)d_in[6];
    float* out = (float*)d_out;

    float *part, *ns2, *attn;
    __half *qh, *kh, *xTh, *yTh, *vTh, *wkvh, *wqTh, *wdwh, *wc2h, *w2h;
    cudaGetSymbolAddress((void**)&part, g_part);
    cudaGetSymbolAddress((void**)&ns2,  g_ns2);
    cudaGetSymbolAddress((void**)&attn, g_attn);
    cudaGetSymbolAddress((void**)&qh,   g_qh);
    cudaGetSymbolAddress((void**)&kh,   g_kh);
    cudaGetSymbolAddress((void**)&xTh,  g_xTh);
    cudaGetSymbolAddress((void**)&yTh,  g_yTh);
    cudaGetSymbolAddress((void**)&vTh,  g_vTh);
    cudaGetSymbolAddress((void**)&wkvh, g_wkvh);
    cudaGetSymbolAddress((void**)&wqTh, g_wqTh);
    cudaGetSymbolAddress((void**)&wdwh, g_wdwh);
    cudaGetSymbolAddress((void**)&wc2h, g_wc2h);
    cudaGetSymbolAddress((void**)&w2h,  g_w2h);

    cudaFuncSetAttribute(hgemm<0,0>, cudaFuncAttributeMaxDynamicSharedMemorySize, SMEMB);
    cudaFuncSetAttribute(hgemm<0,1>, cudaFuncAttributeMaxDynamicSharedMemorySize, SMEMB);
    cudaFuncSetAttribute(hgemm<0,2>, cudaFuncAttributeMaxDynamicSharedMemorySize, SMEMB);
    cudaFuncSetAttribute(hgemm<1,1>, cudaFuncAttributeMaxDynamicSharedMemorySize, SMEMB);
    cudaFuncSetAttribute(attn_mma2, cudaFuncAttributeMaxDynamicSharedMemorySize, ASMEM);

    // ---- ordered so the conv hgemm is launch #6 (ncu captures -s 5 -c 1) ----
    prep_wdw_h<<<512, 256>>>(wdw, wdwh);                                       // 1
    transpose_h<0><<<dim3(16,16,1), 256>>>(wq, 0L, wqTh, 0L, DIM, DIM);        // 2
    ypad_zero_h<<<dim3(260,BATCH), 256>>>(yTh);                                // 3
    transpose_h<1><<<dim3(128,16,BATCH), 256>>>(y, (long)DIM*MLEN, yTh,
                                                (long)YROWS*DIM, DIM, MLEN);   // 4
    hgemm<0,1><<<dim3(4,4,9), 256, SMEMB>>>(
        wdwh, (long)DIM*DIM, wqTh, 0L, wc2h, 512L, KCONV, DIM, DIM, nullptr);  // 5
    hgemm<1,1><<<dim3(32,4,BATCH), 256, SMEMB>>>(
        wc2h, 0L, yTh, (long)YROWS*DIM, qh, (long)DIM*MLEN, MLEN,
        DIM, KCONV, nullptr);                                                  // 6 <- profiled
    conv_h<<<2048, 256>>>(wkv, wkvh, 2*DIM*DIM);                               // 7
    transpose_h<0><<<dim3(128,16,BATCH), 256>>>(x, (long)DIM*MLEN, xTh,
                                                (long)MLEN*DIM, DIM, MLEN);    // 8
    hgemm<0,2><<<dim3(32,8,BATCH), 256, SMEMB>>>(
        wkvh, 0L, xTh, (long)MLEN*DIM, kh, (long)DIM*MLEN, MLEN,
        2*DIM, DIM, vTh);                                                      // 9
    nsq_kernel<<<512, 256>>>(qh, kh, ns2);                                     // 10
    attn_mma2<<<dim3(8,HEADS,BATCH), 256, ASMEM>>>(qh, kh, part);              // 11
    softmax_kernel<<<BATCH*HEADS*HD, 32>>>(part, ns2, temp, attn);             // 12
    w2_kernel_h<<<dim3(128,HEADS,BATCH), 256>>>(wout, attn, w2h);              // 13
    hgemm<0,0><<<dim3(32,4,BATCH), 256, SMEMB>>>(
        w2h, (long)DIM*DIM, vTh, (long)MLEN*DIM, out, (long)DIM*MLEN, MLEN,
        DIM, DIM, nullptr);                                                    // 14
}